// round 10
// baseline (speedup 1.0000x reference)
#include <cuda_runtime.h>
#include <math.h>
#include <stdint.h>

// Problem constants
#define NN 9216      // H*W = 96*96
#define CC 64        // channels
#define C8 8         // C/8
#define BB 2         // batch
#define KT 32        // key tile
#define NT (NN / KT) // 288 tiles
#define PITCH 20     // b32 pitch of transposed h tiles [c][k/2], 16 data + 4 pad

// -------- scratch (static device globals: no runtime allocation) ----------
__device__ float d_invsig[3];                       // 1/sigma for Wq, Wk, Wv
__device__ float d_f[BB * NN * C8];                 // raw keys    f~ = Wq x
__device__ float d_g[BB * NN * C8];                 // raw queries g~ = Wk x
__device__ float d_h[BB * NN * CC];                 // raw values  h~ = Wv x
__device__ float d_fmax2[72];                       // per-prep-block max ||f~||^2

// ---------------- bf16 helpers -----------------
__device__ __forceinline__ uint32_t pack_bf16(float hi, float lo) {
    uint32_t r;
    asm("cvt.rn.bf16x2.f32 %0, %1, %2;" : "=r"(r) : "f"(hi), "f"(lo));
    return r;
}
__device__ __forceinline__ float bf_lo(uint32_t u) {
    return __uint_as_float(u << 16);
}
__device__ __forceinline__ float bf_hi(uint32_t u) {
    return __uint_as_float(u & 0xffff0000u);
}
__device__ __forceinline__ void ldsm4(uint32_t& a0, uint32_t& a1,
                                      uint32_t& a2, uint32_t& a3, uint32_t addr) {
    asm volatile("ldmatrix.sync.aligned.m8n8.x4.shared.b16 {%0,%1,%2,%3}, [%4];"
                 : "=r"(a0), "=r"(a1), "=r"(a2), "=r"(a3) : "r"(addr));
}
__device__ __forceinline__ void mma16(float* d,
        uint32_t a0, uint32_t a1, uint32_t a2, uint32_t a3,
        uint32_t b0, uint32_t b1) {
    asm volatile(
        "mma.sync.aligned.m16n8k16.row.col.f32.bf16.bf16.f32 "
        "{%0,%1,%2,%3},{%4,%5,%6,%7},{%8,%9},{%0,%1,%2,%3};"
        : "+f"(d[0]), "+f"(d[1]), "+f"(d[2]), "+f"(d[3])
        : "r"(a0), "r"(a1), "r"(a2), "r"(a3), "r"(b0), "r"(b1));
}
__device__ __forceinline__ uint32_t smem_u32(const void* p) {
    uint32_t a;
    asm("{ .reg .u64 t; cvta.to.shared.u64 t, %1; cvt.u32.u64 %0, t; }"
        : "=r"(a) : "l"(p));
    return a;
}

// ===========================================================================
// K1 (merged): blocks 0-2 spectral norm (squaring + short power iteration);
// blocks 3-74 raw projections + per-block max ||f~||^2.
// ===========================================================================
#define SQ_ITERS 4
#define PW_ITERS 16

__global__ void __launch_bounds__(256) prep_kernel(
        const float* __restrict__ x,
        const float* __restrict__ Wq,
        const float* __restrict__ Wk,
        const float* __restrict__ Wv) {
    __shared__ float shb[8704];
    __shared__ float part[8];
    __shared__ float scal;
    int t = threadIdx.x;

    if (blockIdx.x < 3) {
        int mat = blockIdx.x;
        const float* W = (mat == 0) ? Wq : (mat == 1) ? Wk : Wv;
        int dim = (mat == 2) ? 64 : 8;
        float* Ga = shb;                 // 64*65
        float* Gb = shb + 4160;          // 64*65 (also W staging)
        float* vv = shb + 8320;          // 64

        for (int i = t; i < dim * 64; i += 256)
            Gb[(i >> 6) * 65 + (i & 63)] = W[i];
        __syncthreads();

        if (dim == 64) {
            int r = t >> 2, c0 = (t & 3) << 4;
            float rr[64];
#pragma unroll
            for (int j = 0; j < 64; j++) rr[j] = Gb[r * 65 + j];
            float acc[16];
#pragma unroll
            for (int cc = 0; cc < 16; cc++) acc[cc] = 0.f;
            for (int j = 0; j < 64; j++)
#pragma unroll
                for (int cc = 0; cc < 16; cc++)
                    acc[cc] += rr[j] * Gb[(c0 + cc) * 65 + j];
#pragma unroll
            for (int cc = 0; cc < 16; cc++) Ga[r * 65 + c0 + cc] = acc[cc];
        } else if (t < 64) {
            int r = t >> 3, c = t & 7;
            float s = 0.f;
            for (int j = 0; j < 64; j++) s += Gb[r * 65 + j] * Gb[c * 65 + j];
            Ga[r * 65 + c] = s;
        }
        __syncthreads();

        float logl = 0.f, pw = 1.f;
        float* src = Ga;
        float* dst = Gb;
        for (int it = 0; it < SQ_ITERS; it++) {
            float ss = 0.f;
            for (int e = t; e < dim * dim; e += 256) {
                float v = src[(e / dim) * 65 + (e % dim)];
                ss += v * v;
            }
#pragma unroll
            for (int o = 16; o > 0; o >>= 1)
                ss += __shfl_xor_sync(0xffffffffu, ss, o);
            if ((t & 31) == 0) part[t >> 5] = ss;
            __syncthreads();
            float tot = 0.f;
#pragma unroll
            for (int i = 0; i < 8; i++) tot += part[i];
            float fro = sqrtf(tot);
            float inv2 = 1.f / tot;
            logl += log2f(fro) * pw;
            pw *= 0.5f;

            if (dim == 64) {
                int r = t >> 2, c0 = (t & 3) << 4;
                float rr[64];
#pragma unroll
                for (int j = 0; j < 64; j++) rr[j] = src[r * 65 + j];
                float acc[16];
#pragma unroll
                for (int cc = 0; cc < 16; cc++) acc[cc] = 0.f;
                for (int j = 0; j < 64; j++)
#pragma unroll
                    for (int cc = 0; cc < 16; cc++)
                        acc[cc] += rr[j] * src[j * 65 + c0 + cc];
#pragma unroll
                for (int cc = 0; cc < 16; cc++)
                    dst[r * 65 + c0 + cc] = acc[cc] * inv2;
            } else if (t < 64) {
                int r = t >> 3, c = t & 7;
                float s = 0.f;
#pragma unroll
                for (int j = 0; j < 8; j++) s += src[r * 65 + j] * src[j * 65 + c];
                dst[r * 65 + c] = s * inv2;
            }
            __syncthreads();
            float* tmp = src; src = dst; dst = tmp;
        }

        if (t < dim) vv[t] = 1.f;
        __syncthreads();
        float lam = 1.f;
        for (int it = 0; it < PW_ITERS; it++) {
            float w = 0.f;
            if (t < dim) {
                const float* gr = src + t * 65;
                for (int j = 0; j < dim; j++) w += gr[j] * vv[j];
            }
            float sq = w * w;
#pragma unroll
            for (int o = 16; o > 0; o >>= 1)
                sq += __shfl_xor_sync(0xffffffffu, sq, o);
            if ((t & 31) == 0) part[t >> 5] = sq;
            __syncthreads();
            if (t == 0) scal = sqrtf(part[0] + part[1]);
            __syncthreads();
            lam = scal;
            if (t < dim) vv[t] = w / lam;
            __syncthreads();
        }
        if (t == 0) {
            float l0 = log2f(lam) * pw + logl;
            d_invsig[mat] = exp2f(-0.5f * l0);
        }
    } else {
        float* wq = shb;            // 512
        float* wk = shb + 512;      // 512
        float* wv = shb + 1024;     // 4096

        for (int i = t; i < 512; i += 256) { wq[i] = Wq[i]; wk[i] = Wk[i]; }
        for (int i = t; i < 4096; i += 256) wv[i] = Wv[i];
        __syncthreads();

        int gid = (blockIdx.x - 3) * 256 + t;       // 0 .. 18431
        int b = gid / NN, n = gid % NN;

        float fa[8] = {0.f}, ga[8] = {0.f}, ha[64] = {0.f};
        const float* xp = x + (size_t)b * CC * NN + n;
        for (int c = 0; c < 64; c++) {
            float xc = xp[(size_t)c * NN];
#pragma unroll
            for (int o = 0; o < 8; o++) {
                fa[o] += wq[o * 64 + c] * xc;
                ga[o] += wk[o * 64 + c] * xc;
            }
#pragma unroll
            for (int o = 0; o < 64; o++) ha[o] += wv[o * 64 + c] * xc;
        }

        size_t b8 = ((size_t)b * NN + n) * 8;
#pragma unroll
        for (int o = 0; o < 8; o++) { d_f[b8 + o] = fa[o]; d_g[b8 + o] = ga[o]; }
        size_t b64 = ((size_t)b * NN + n) * 64;
#pragma unroll
        for (int o = 0; o < 64; o++) d_h[b64 + o] = ha[o];

        // block max of ||f~||^2 for the softmax shift bound
        float n2 = 0.f;
#pragma unroll
        for (int o = 0; o < 8; o++) n2 += fa[o] * fa[o];
#pragma unroll
        for (int o = 16; o > 0; o >>= 1)
            n2 = fmaxf(n2, __shfl_xor_sync(0xffffffffu, n2, o));
        if ((t & 31) == 0) part[t >> 5] = n2;
        __syncthreads();
        if (t == 0) {
            float m = part[0];
#pragma unroll
            for (int i = 1; i < 8; i++) m = fmaxf(m, part[i]);
            d_fmax2[blockIdx.x - 3] = m;
        }
    }
}

// ===========================================================================
// K2: single-pass flash attention on bf16 tensor cores.
//   Softmax shift m(n) = iq*Fmax*||g(n)|| + bq.g(n)  (provable upper bound,
//   softmax is shift invariant; no key sweep needed).
//   Per 32-key tile: stage H^T hi/lo bf16 [c][k] (double buffered) ->
//   each warp computes P for its 8 queries directly in B-fragment layout ->
//   mma m16n8k16 x (4 c-tiles x 2 k-steps x 3 split-products).
//   l accumulates per lane, reduced by 2 shuffles. Epilogue from D frags.
// 8 warps: warp w owns q-cols [8w, 8w+8), all 64 c rows.
// ===========================================================================
__global__ void __launch_bounds__(256, 2) attn_kernel(
        const float* __restrict__ x,
        const float* __restrict__ bq,
        const float* __restrict__ bk,
        const float* __restrict__ bv,
        const float* __restrict__ gamma,
        float* __restrict__ out) {
    __shared__ __align__(16) uint32_t h_hi[2][64 * PITCH];
    __shared__ __align__(16) uint32_t h_lo[2][64 * PITCH];
    __shared__ float g_sh[64 * 9];
    __shared__ float red8[8];
    __shared__ float l_sh[64];

    int t    = threadIdx.x;
    int wid  = t >> 5;
    int lane = t & 31;
    int b    = blockIdx.y;
    int qt   = blockIdx.x;

    float iq = d_invsig[0], ik = d_invsig[1], iv = d_invsig[2];

    // stage g tile (scaled + bias)
    const float* gp = d_g + ((size_t)b * NN + qt * 64) * 8;
    for (int i = t; i < 512; i += 256)
        g_sh[(i >> 3) * 9 + (i & 7)] = ik * gp[i] + __ldg(bk + (i & 7));

    // global Fmax^2 reduction (72 values)
    {
        float fm = 0.f;
        if (t < 72) fm = d_fmax2[t];
#pragma unroll
        for (int o = 16; o > 0; o >>= 1)
            fm = fmaxf(fm, __shfl_xor_sync(0xffffffffu, fm, o));
        if (lane == 0) red8[wid] = fm;
    }
    __syncthreads();
    float Fmax;
    {
        float fm = red8[0];
#pragma unroll
        for (int i = 1; i < 8; i++) fm = fmaxf(fm, red8[i]);
        Fmax = sqrtf(fm);
    }

    // per-lane query: n = 8*wid + (lane>>2)
    int nloc = 8 * wid + (lane >> 2);
    int a = lane & 3;
    float gq[8];
    float cq = 0.f, gn2 = 0.f;
#pragma unroll
    for (int d = 0; d < 8; d++) {
        gq[d] = g_sh[nloc * 9 + d];
        cq  += __ldg(bq + d) * gq[d];
        gn2 += gq[d] * gq[d];
    }
    float mshift = iq * Fmax * sqrtf(gn2) + cq;   // >= every score for this n
    float cqm = cq - mshift;

    // ---- H staging helpers (thread roles) ----
    int kp = t & 15;            // k-pair index 0..15
    int cg = t >> 4;            // c-group 0..15 -> c = 4*cg..4*cg+3
    const float4* bv4 = (const float4*)bv;
    float4 bb = __ldg(bv4 + cg);

    // stage tile 0
    {
        const float* hp = d_h + ((size_t)b * NN + 0) * 64;
        float4 v0 = *(const float4*)(hp + (2 * kp) * 64 + cg * 4);
        float4 v1 = *(const float4*)(hp + (2 * kp + 1) * 64 + cg * 4);
        v0.x = iv * v0.x + bb.x; v0.y = iv * v0.y + bb.y;
        v0.z = iv * v0.z + bb.z; v0.w = iv * v0.w + bb.w;
        v1.x = iv * v1.x + bb.x; v1.y = iv * v1.y + bb.y;
        v1.z = iv * v1.z + bb.z; v1.w = iv * v1.w + bb.w;
        float p0[4] = {v0.x, v0.y, v0.z, v0.w};
        float p1[4] = {v1.x, v1.y, v1.z, v1.w};
#pragma unroll
        for (int c = 0; c < 4; c++) {
            uint32_t hi = pack_bf16(p1[c], p0[c]);
            uint32_t lo = pack_bf16(p1[c] - bf_hi(hi), p0[c] - bf_lo(hi));
            h_hi[0][(cg * 4 + c) * PITCH + kp] = hi;
            h_lo[0][(cg * 4 + c) * PITCH + kp] = lo;
        }
    }
    __syncthreads();

    // mma state
    float acc[4][4];
#pragma unroll
    for (int i = 0; i < 4; i++)
#pragma unroll
        for (int j = 0; j < 4; j++) acc[i][j] = 0.f;
    float lsum = 0.f;

    uint32_t hi_base = smem_u32(&h_hi[0][0]);
    uint32_t lo_base = smem_u32(&h_lo[0][0]);
    int rb  = ((lane >> 3) & 1) * 8 + (lane & 7);   // row within 16-c tile
    int kob = (lane >> 4) * 16;                     // 0 or +16 bytes (k half)
    uint32_t frag_off = (uint32_t)(rb * (PITCH * 4) + kob);

    const float4* f4b = (const float4*)(d_f + (size_t)b * NN * 8);

    for (int kt = 0; kt < NT; kt++) {
        int cur = kt & 1;

        // prefetch next H tile into registers
        float4 nv0, nv1;
        if (kt + 1 < NT) {
            const float* hp = d_h + ((size_t)b * NN + (kt + 1) * KT) * 64;
            nv0 = *(const float4*)(hp + (2 * kp) * 64 + cg * 4);
            nv1 = *(const float4*)(hp + (2 * kp + 1) * 64 + cg * 4);
        }

        // ---- scores -> P in B-fragment layout (registers only) ----
        uint32_t bh[2][2], bl[2][2];
        const float4* f4 = f4b + (size_t)kt * KT * 2;
#pragma unroll
        for (int ks = 0; ks < 2; ks++) {
#pragma unroll
            for (int half = 0; half < 2; half++) {
                int r0 = 16 * ks + 2 * a + 8 * half;
                float4 A0 = __ldg(f4 + r0 * 2);
                float4 A1 = __ldg(f4 + r0 * 2 + 1);
                float4 B0 = __ldg(f4 + (r0 + 1) * 2);
                float4 B1 = __ldg(f4 + (r0 + 1) * 2 + 1);
                float s0 = A0.x * gq[0] + A0.y * gq[1] + A0.z * gq[2] + A0.w * gq[3]
                         + A1.x * gq[4] + A1.y * gq[5] + A1.z * gq[6] + A1.w * gq[7];
                float s1 = B0.x * gq[0] + B0.y * gq[1] + B0.z * gq[2] + B0.w * gq[3]
                         + B1.x * gq[4] + B1.y * gq[5] + B1.z * gq[6] + B1.w * gq[7];
                float p0 = __expf(iq * s0 + cqm);
                float p1 = __expf(iq * s1 + cqm);
                lsum += p0 + p1;
                uint32_t hi = pack_bf16(p1, p0);
                bh[ks][half] = hi;
                bl[ks][half] = pack_bf16(p1 - bf_hi(hi), p0 - bf_lo(hi));
            }
        }

        // ---- tensor-core O += H @ P ----
        uint32_t hb = hi_base + cur * (64 * PITCH * 4) + frag_off;
        uint32_t lb = lo_base + cur * (64 * PITCH * 4) + frag_off;
#pragma unroll
        for (int ct = 0; ct < 4; ct++) {
            uint32_t rowb = (uint32_t)(ct * 16 * PITCH * 4);
#pragma unroll
            for (int ks = 0; ks < 2; ks++) {
                uint32_t ah0, ah1, ah2, ah3, al0, al1, al2, al3;
                ldsm4(ah0, ah1, ah2, ah3, hb + rowb + ks * 32);
                ldsm4(al0, al1, al2, al3, lb + rowb + ks * 32);
                mma16(acc[ct], ah0, ah1, ah2, ah3, bh[ks][0], bh[ks][1]);
                mma16(acc[ct], ah0, ah1, ah2, ah3, bl[ks][0], bl[ks][1]);
                mma16(acc[ct], al0, al1, al2, al3, bh[ks][0], bh[ks][1]);
            }
        }

        // ---- convert + store next tile ----
        if (kt + 1 < NT) {
            nv0.x = iv * nv0.x + bb.x; nv0.y = iv * nv0.y + bb.y;
            nv0.z = iv * nv0.z + bb.z; nv0.w = iv * nv0.w + bb.w;
            nv1.x = iv * nv1.x + bb.x; nv1.y = iv * nv1.y + bb.y;
            nv1.z = iv * nv1.z + bb.z; nv1.w = iv * nv1.w + bb.w;
            float p0[4] = {nv0.x, nv0.y, nv0.z, nv0.w};
            float p1[4] = {nv1.x, nv1.y, nv1.z, nv1.w};
            int nb = cur ^ 1;
#pragma unroll
            for (int c = 0; c < 4; c++) {
                uint32_t hi = pack_bf16(p1[c], p0[c]);
                uint32_t lo = pack_bf16(p1[c] - bf_hi(hi), p0[c] - bf_lo(hi));
                h_hi[nb][(cg * 4 + c) * PITCH + kp] = hi;
                h_lo[nb][(cg * 4 + c) * PITCH + kp] = lo;
            }
        }
        __syncthreads();
    }

    // ---- denominator: reduce over the 4 lanes sharing a query ----
    lsum += __shfl_xor_sync(0xffffffffu, lsum, 1);
    lsum += __shfl_xor_sync(0xffffffffu, lsum, 2);
    l_sh[nloc] = 1.f / lsum;
    __syncwarp();
    int q0 = 8 * wid + 2 * a;
    float li0 = l_sh[q0], li1 = l_sh[q0 + 1];

    // ---- epilogue from D fragments ----
    float gam = gamma[0];
#pragma unroll
    for (int ct = 0; ct < 4; ct++) {
        int c0 = ct * 16 + (lane >> 2);
        size_t base0 = ((size_t)b * CC + c0) * NN + (size_t)qt * 64 + q0;
        float2 x0 = *(const float2*)(x + base0);
        float2 r0;
        r0.x = gam * acc[ct][0] * li0 + x0.x;
        r0.y = gam * acc[ct][1] * li1 + x0.y;
        *(float2*)(out + base0) = r0;

        size_t base1 = base0 + (size_t)8 * NN;
        float2 x1 = *(const float2*)(x + base1);
        float2 r1;
        r1.x = gam * acc[ct][2] * li0 + x1.x;
        r1.y = gam * acc[ct][3] * li1 + x1.y;
        *(float2*)(out + base1) = r1;
    }
}

// ===========================================================================
extern "C" void kernel_launch(void* const* d_in, const int* in_sizes, int n_in,
                              void* d_out, int out_size) {
    const float* x     = (const float*)d_in[0];
    const float* Wq    = (const float*)d_in[1];
    const float* bq    = (const float*)d_in[2];
    const float* Wk    = (const float*)d_in[3];
    const float* bk    = (const float*)d_in[4];
    const float* Wv    = (const float*)d_in[5];
    const float* bv    = (const float*)d_in[6];
    const float* gamma = (const float*)d_in[7];
    float* out = (float*)d_out;

    prep_kernel<<<3 + (BB * NN) / 256, 256>>>(x, Wq, Wk, Wv);
    attn_kernel<<<dim3(NN / 64, BB), 256>>>(x, bq, bk, bv, gamma, out);
}

// round 11
// speedup vs baseline: 1.7425x; 1.7425x over previous
#include <cuda_runtime.h>
#include <cuda_fp16.h>
#include <math.h>
#include <stdint.h>

// Problem constants
#define NN 9216      // H*W = 96*96
#define CC 64        // channels
#define C8 8         // C/8
#define BB 2         // batch
#define KT 32        // key tile
#define NT (NN / KT) // 288 tiles
#define PITCH 20     // b32 pitch of H tiles [c][k-pair]: 16 data + 4 pad
#define SHIFT 9.70406053f   // 14*ln2: P scaled by 2^14 (cancels in O/l)

// -------- scratch (static device globals: no runtime allocation) ----------
__device__ float d_invsig[3];                       // 1/sigma for Wq, Wk, Wv
__device__ float d_f[BB * NN * C8];                 // raw keys    f~ = Wq x
__device__ float d_g[BB * NN * C8];                 // raw queries g~ = Wk x
__device__ float d_h[BB * NN * CC];                 // raw values  h~ = Wv x
__device__ float d_fmax2[72];                       // per-prep-block max ||f~||^2

// ---------------- helpers -----------------
__device__ __forceinline__ uint32_t to_tf32(float x) {
    uint32_t u;
    asm("cvt.rna.tf32.f32 %0, %1;" : "=r"(u) : "f"(x));
    return u;
}
__device__ __forceinline__ uint32_t pack_f16(float hi, float lo) {
    uint32_t r;
    asm("cvt.rn.f16x2.f32 %0, %1, %2;" : "=r"(r) : "f"(hi), "f"(lo));
    return r;
}
__device__ __forceinline__ uint32_t movm(uint32_t s) {
    uint32_t d;
    asm("movmatrix.sync.aligned.m8n8.trans.b16 %0, %1;" : "=r"(d) : "r"(s));
    return d;
}
__device__ __forceinline__ void ldsm4(uint32_t& a0, uint32_t& a1,
                                      uint32_t& a2, uint32_t& a3, uint32_t addr) {
    asm volatile("ldmatrix.sync.aligned.m8n8.x4.shared.b16 {%0,%1,%2,%3}, [%4];"
                 : "=r"(a0), "=r"(a1), "=r"(a2), "=r"(a3) : "r"(addr));
}
// tf32 m16n8k8 (score GEMM)
__device__ __forceinline__ void mma8(float* d,
        uint32_t a0, uint32_t a1, uint32_t a2, uint32_t a3,
        uint32_t b0, uint32_t b1) {
    asm volatile(
        "mma.sync.aligned.m16n8k8.row.col.f32.tf32.tf32.f32 "
        "{%0,%1,%2,%3},{%4,%5,%6,%7},{%8,%9},{%0,%1,%2,%3};"
        : "+f"(d[0]), "+f"(d[1]), "+f"(d[2]), "+f"(d[3])
        : "r"(a0), "r"(a1), "r"(a2), "r"(a3), "r"(b0), "r"(b1));
}
// fp16 m16n8k16 (PV GEMM)
__device__ __forceinline__ void mma16h(float* d,
        uint32_t a0, uint32_t a1, uint32_t a2, uint32_t a3,
        uint32_t b0, uint32_t b1) {
    asm volatile(
        "mma.sync.aligned.m16n8k16.row.col.f32.f16.f16.f32 "
        "{%0,%1,%2,%3},{%4,%5,%6,%7},{%8,%9},{%0,%1,%2,%3};"
        : "+f"(d[0]), "+f"(d[1]), "+f"(d[2]), "+f"(d[3])
        : "r"(a0), "r"(a1), "r"(a2), "r"(a3), "r"(b0), "r"(b1));
}
__device__ __forceinline__ uint32_t smem_u32(const void* p) {
    uint32_t a;
    asm("{ .reg .u64 t; cvta.to.shared.u64 t, %1; cvt.u32.u64 %0, t; }"
        : "=r"(a) : "l"(p));
    return a;
}

// ===========================================================================
// K1 (merged): blocks 0-2 spectral norm (squaring + short power iteration);
// blocks 3-74 raw projections + per-block max ||f~||^2.
// ===========================================================================
#define SQ_ITERS 4
#define PW_ITERS 16

__global__ void __launch_bounds__(256) prep_kernel(
        const float* __restrict__ x,
        const float* __restrict__ Wq,
        const float* __restrict__ Wk,
        const float* __restrict__ Wv) {
    __shared__ float shb[8704];
    __shared__ float part[8];
    __shared__ float scal;
    int t = threadIdx.x;

    if (blockIdx.x < 3) {
        int mat = blockIdx.x;
        const float* W = (mat == 0) ? Wq : (mat == 1) ? Wk : Wv;
        int dim = (mat == 2) ? 64 : 8;
        float* Ga = shb;                 // 64*65
        float* Gb = shb + 4160;          // 64*65 (also W staging)
        float* vv = shb + 8320;          // 64

        for (int i = t; i < dim * 64; i += 256)
            Gb[(i >> 6) * 65 + (i & 63)] = W[i];
        __syncthreads();

        if (dim == 64) {
            int r = t >> 2, c0 = (t & 3) << 4;
            float rr[64];
#pragma unroll
            for (int j = 0; j < 64; j++) rr[j] = Gb[r * 65 + j];
            float acc[16];
#pragma unroll
            for (int cc = 0; cc < 16; cc++) acc[cc] = 0.f;
            for (int j = 0; j < 64; j++)
#pragma unroll
                for (int cc = 0; cc < 16; cc++)
                    acc[cc] += rr[j] * Gb[(c0 + cc) * 65 + j];
#pragma unroll
            for (int cc = 0; cc < 16; cc++) Ga[r * 65 + c0 + cc] = acc[cc];
        } else if (t < 64) {
            int r = t >> 3, c = t & 7;
            float s = 0.f;
            for (int j = 0; j < 64; j++) s += Gb[r * 65 + j] * Gb[c * 65 + j];
            Ga[r * 65 + c] = s;
        }
        __syncthreads();

        float logl = 0.f, pw = 1.f;
        float* src = Ga;
        float* dst = Gb;
        for (int it = 0; it < SQ_ITERS; it++) {
            float ss = 0.f;
            for (int e = t; e < dim * dim; e += 256) {
                float v = src[(e / dim) * 65 + (e % dim)];
                ss += v * v;
            }
#pragma unroll
            for (int o = 16; o > 0; o >>= 1)
                ss += __shfl_xor_sync(0xffffffffu, ss, o);
            if ((t & 31) == 0) part[t >> 5] = ss;
            __syncthreads();
            float tot = 0.f;
#pragma unroll
            for (int i = 0; i < 8; i++) tot += part[i];
            float fro = sqrtf(tot);
            float inv2 = 1.f / tot;
            logl += log2f(fro) * pw;
            pw *= 0.5f;

            if (dim == 64) {
                int r = t >> 2, c0 = (t & 3) << 4;
                float rr[64];
#pragma unroll
                for (int j = 0; j < 64; j++) rr[j] = src[r * 65 + j];
                float acc[16];
#pragma unroll
                for (int cc = 0; cc < 16; cc++) acc[cc] = 0.f;
                for (int j = 0; j < 64; j++)
#pragma unroll
                    for (int cc = 0; cc < 16; cc++)
                        acc[cc] += rr[j] * src[j * 65 + c0 + cc];
#pragma unroll
                for (int cc = 0; cc < 16; cc++)
                    dst[r * 65 + c0 + cc] = acc[cc] * inv2;
            } else if (t < 64) {
                int r = t >> 3, c = t & 7;
                float s = 0.f;
#pragma unroll
                for (int j = 0; j < 8; j++) s += src[r * 65 + j] * src[j * 65 + c];
                dst[r * 65 + c] = s * inv2;
            }
            __syncthreads();
            float* tmp = src; src = dst; dst = tmp;
        }

        if (t < dim) vv[t] = 1.f;
        __syncthreads();
        float lam = 1.f;
        for (int it = 0; it < PW_ITERS; it++) {
            float w = 0.f;
            if (t < dim) {
                const float* gr = src + t * 65;
                for (int j = 0; j < dim; j++) w += gr[j] * vv[j];
            }
            float sq = w * w;
#pragma unroll
            for (int o = 16; o > 0; o >>= 1)
                sq += __shfl_xor_sync(0xffffffffu, sq, o);
            if ((t & 31) == 0) part[t >> 5] = sq;
            __syncthreads();
            if (t == 0) scal = sqrtf(part[0] + part[1]);
            __syncthreads();
            lam = scal;
            if (t < dim) vv[t] = w / lam;
            __syncthreads();
        }
        if (t == 0) {
            float l0 = log2f(lam) * pw + logl;
            d_invsig[mat] = exp2f(-0.5f * l0);
        }
    } else {
        float* wq = shb;            // 512
        float* wk = shb + 512;      // 512
        float* wv = shb + 1024;     // 4096

        for (int i = t; i < 512; i += 256) { wq[i] = Wq[i]; wk[i] = Wk[i]; }
        for (int i = t; i < 4096; i += 256) wv[i] = Wv[i];
        __syncthreads();

        int gid = (blockIdx.x - 3) * 256 + t;       // 0 .. 18431
        int b = gid / NN, n = gid % NN;

        float fa[8] = {0.f}, ga[8] = {0.f}, ha[64] = {0.f};
        const float* xp = x + (size_t)b * CC * NN + n;
        for (int c = 0; c < 64; c++) {
            float xc = xp[(size_t)c * NN];
#pragma unroll
            for (int o = 0; o < 8; o++) {
                fa[o] += wq[o * 64 + c] * xc;
                ga[o] += wk[o * 64 + c] * xc;
            }
#pragma unroll
            for (int o = 0; o < 64; o++) ha[o] += wv[o * 64 + c] * xc;
        }

        size_t b8 = ((size_t)b * NN + n) * 8;
#pragma unroll
        for (int o = 0; o < 8; o++) { d_f[b8 + o] = fa[o]; d_g[b8 + o] = ga[o]; }
        size_t b64 = ((size_t)b * NN + n) * 64;
#pragma unroll
        for (int o = 0; o < 64; o++) d_h[b64 + o] = ha[o];

        // block max of ||f~||^2 for the softmax shift bound
        float n2 = 0.f;
#pragma unroll
        for (int o = 0; o < 8; o++) n2 += fa[o] * fa[o];
#pragma unroll
        for (int o = 16; o > 0; o >>= 1)
            n2 = fmaxf(n2, __shfl_xor_sync(0xffffffffu, n2, o));
        if ((t & 31) == 0) part[t >> 5] = n2;
        __syncthreads();
        if (t == 0) {
            float m = part[0];
#pragma unroll
            for (int i = 1; i < 8; i++) m = fmaxf(m, part[i]);
            d_fmax2[blockIdx.x - 3] = m;
        }
    }
}

// ===========================================================================
// K2: single-pass flash attention, fully tensor-core.
//   Shift: s - m = iq*(f~.g) - iq*Fmax*||g||  (bq.g cancels); P scaled 2^14.
//   Scores: tf32 m16n8k8 (hi/lo 3-term, exact to ~2^-22) on raw f~ from L2;
//           exp in D-frag registers; movmatrix converts packed P rows into
//           PV B-fragments (hi/lo fp16) -- P never touches smem.
//   PV: H staged as single-plane fp16 [c][k], double buffered; ldsm A frags;
//       O += H*(Phi+Plo) via fp16 m16n8k16.
//   l: per-lane accumulation + 3 shuffles (no smem).
// 8 warps: warp w owns q-cols [8w, 8w+8), all 64 c rows.
// ===========================================================================
__global__ void __launch_bounds__(256, 2) attn_kernel(
        const float* __restrict__ x,
        const float* __restrict__ bq,
        const float* __restrict__ bk,
        const float* __restrict__ bv,
        const float* __restrict__ gamma,
        float* __restrict__ out) {
    __shared__ __align__(16) uint32_t h_s[2][64 * PITCH];   // fp16 H [c][k]
    __shared__ float g_sh[64 * 9];
    __shared__ float red8[8];

    int t    = threadIdx.x;
    int wid  = t >> 5;
    int lane = t & 31;
    int b    = blockIdx.y;
    int qt   = blockIdx.x;

    float iq = d_invsig[0], ik = d_invsig[1], iv = d_invsig[2];

    // stage g tile (scaled + bias)
    const float* gp = d_g + ((size_t)b * NN + qt * 64) * 8;
    for (int i = t; i < 512; i += 256)
        g_sh[(i >> 3) * 9 + (i & 7)] = ik * gp[i] + __ldg(bk + (i & 7));

    // global Fmax^2 reduction (72 values)
    {
        float fm = 0.f;
        if (t < 72) fm = d_fmax2[t];
#pragma unroll
        for (int o = 16; o > 0; o >>= 1)
            fm = fmaxf(fm, __shfl_xor_sync(0xffffffffu, fm, o));
        if (lane == 0) red8[wid] = fm;
    }
    __syncthreads();
    float Fmax;
    {
        float fm = red8[0];
#pragma unroll
        for (int i = 1; i < 8; i++) fm = fmaxf(fm, red8[i]);
        Fmax = sqrtf(fm);
    }

    // G B-fragments (tf32 hi/lo), loaded once: b0=(d=l&3, q=l>>2), b1=d+4
    uint32_t Ghi0, Ghi1, Glo0, Glo1;
    {
        int qn = 8 * wid + (lane >> 2);
        float g0 = g_sh[qn * 9 + (lane & 3)];
        float g1 = g_sh[qn * 9 + (lane & 3) + 4];
        Ghi0 = to_tf32(g0); Glo0 = to_tf32(g0 - __uint_as_float(Ghi0));
        Ghi1 = to_tf32(g1); Glo1 = to_tf32(g1 - __uint_as_float(Ghi1));
    }

    // exponent constants for this lane's two q columns (qa, qa+1)
    int qa = 8 * wid + 2 * (lane & 3);
    float cqm0, cqm1;
    {
        float n20 = 0.f, n21 = 0.f;
#pragma unroll
        for (int d = 0; d < 8; d++) {
            float v0 = g_sh[qa * 9 + d];
            float v1 = g_sh[(qa + 1) * 9 + d];
            n20 += v0 * v0;
            n21 += v1 * v1;
        }
        cqm0 = SHIFT - iq * Fmax * sqrtf(n20);
        cqm1 = SHIFT - iq * Fmax * sqrtf(n21);
    }

    // ---- H staging roles ----
    int kp = t & 15;            // k-pair index 0..15
    int cg = t >> 4;            // c-group 0..15 -> c = 4*cg..4*cg+3
    const float4* bv4 = (const float4*)bv;
    float4 bb = __ldg(bv4 + cg);

    // stage tile 0 (single fp16 plane)
    {
        const float* hp = d_h + (size_t)b * NN * 64;
        float4 v0 = *(const float4*)(hp + (2 * kp) * 64 + cg * 4);
        float4 v1 = *(const float4*)(hp + (2 * kp + 1) * 64 + cg * 4);
        float p0[4] = {iv * v0.x + bb.x, iv * v0.y + bb.y,
                       iv * v0.z + bb.z, iv * v0.w + bb.w};
        float p1[4] = {iv * v1.x + bb.x, iv * v1.y + bb.y,
                       iv * v1.z + bb.z, iv * v1.w + bb.w};
#pragma unroll
        for (int c = 0; c < 4; c++)
            h_s[0][(cg * 4 + c) * PITCH + kp] = pack_f16(p1[c], p0[c]);
    }
    __syncthreads();

    float acc[4][4];
#pragma unroll
    for (int i = 0; i < 4; i++)
#pragma unroll
        for (int j = 0; j < 4; j++) acc[i][j] = 0.f;
    float lsum0 = 0.f, lsum1 = 0.f;

    uint32_t h_base = smem_u32(&h_s[0][0]);
    int rb  = ((lane >> 3) & 1) * 8 + (lane & 7);
    int kob = (lane >> 4) * 16;
    uint32_t frag_off = (uint32_t)(rb * (PITCH * 4) + kob);

    const float* fbase = d_f + (size_t)b * NN * 8;
    int fr = (lane >> 2) * 8 + (lane & 3);          // f-tile lane offset

    for (int kt = 0; kt < NT; kt++) {
        int cur = kt & 1;

        // prefetch next H tile
        float4 nv0, nv1;
        if (kt + 1 < NT) {
            const float* hp = d_h + ((size_t)b * NN + (kt + 1) * KT) * 64;
            nv0 = *(const float4*)(hp + (2 * kp) * 64 + cg * 4);
            nv1 = *(const float4*)(hp + (2 * kp + 1) * 64 + cg * 4);
        }

        // ---- scores on tensor cores -> P B-frags in registers ----
        uint32_t Bh[2][2], Bl[2][2];
#pragma unroll
        for (int mt = 0; mt < 2; mt++) {
            const float* fp = fbase + (size_t)(kt * KT + mt * 16) * 8;
            float a0 = __ldg(fp + fr);
            float a1 = __ldg(fp + fr + 64);
            float a2 = __ldg(fp + fr + 4);
            float a3 = __ldg(fp + fr + 68);
            uint32_t Ah0 = to_tf32(a0), Ah1 = to_tf32(a1);
            uint32_t Ah2 = to_tf32(a2), Ah3 = to_tf32(a3);
            uint32_t Al0 = to_tf32(a0 - __uint_as_float(Ah0));
            uint32_t Al1 = to_tf32(a1 - __uint_as_float(Ah1));
            uint32_t Al2 = to_tf32(a2 - __uint_as_float(Ah2));
            uint32_t Al3 = to_tf32(a3 - __uint_as_float(Ah3));

            float D[4] = {0.f, 0.f, 0.f, 0.f};
            mma8(D, Ah0, Ah1, Ah2, Ah3, Ghi0, Ghi1);
            mma8(D, Ah0, Ah1, Ah2, Ah3, Glo0, Glo1);
            mma8(D, Al0, Al1, Al2, Al3, Ghi0, Ghi1);

            float p0 = __expf(fmaf(iq, D[0], cqm0));
            float p1 = __expf(fmaf(iq, D[1], cqm1));
            float p2 = __expf(fmaf(iq, D[2], cqm0));
            float p3 = __expf(fmaf(iq, D[3], cqm1));
            lsum0 += p0 + p2;
            lsum1 += p1 + p3;

            uint32_t uA = pack_f16(p1, p0);      // rows 0-7 (lo=col even)
            uint32_t uB = pack_f16(p3, p2);      // rows 8-15
            Bh[mt][0] = movm(uA);
            Bh[mt][1] = movm(uB);
            __half2 hA = *(__half2*)&uA;
            __half2 hB = *(__half2*)&uB;
            uint32_t lA = pack_f16(p1 - __half2float(hA.y),
                                   p0 - __half2float(hA.x));
            uint32_t lB = pack_f16(p3 - __half2float(hB.y),
                                   p2 - __half2float(hB.x));
            Bl[mt][0] = movm(lA);
            Bl[mt][1] = movm(lB);
        }

        // ---- PV: O += H * (Phi + Plo) ----
        uint32_t hb = h_base + cur * (64 * PITCH * 4) + frag_off;
#pragma unroll
        for (int ct = 0; ct < 4; ct++) {
            uint32_t rowb = (uint32_t)(ct * 16 * PITCH * 4);
#pragma unroll
            for (int ks = 0; ks < 2; ks++) {
                uint32_t a0, a1, a2, a3;
                ldsm4(a0, a1, a2, a3, hb + rowb + ks * 32);
                mma16h(acc[ct], a0, a1, a2, a3, Bh[ks][0], Bh[ks][1]);
                mma16h(acc[ct], a0, a1, a2, a3, Bl[ks][0], Bl[ks][1]);
            }
        }

        // ---- convert + store next tile ----
        if (kt + 1 < NT) {
            float p0[4] = {iv * nv0.x + bb.x, iv * nv0.y + bb.y,
                           iv * nv0.z + bb.z, iv * nv0.w + bb.w};
            float p1[4] = {iv * nv1.x + bb.x, iv * nv1.y + bb.y,
                           iv * nv1.z + bb.z, iv * nv1.w + bb.w};
            int nb = cur ^ 1;
#pragma unroll
            for (int c = 0; c < 4; c++)
                h_s[nb][(cg * 4 + c) * PITCH + kp] = pack_f16(p1[c], p0[c]);
        }
        __syncthreads();
    }

    // ---- denominator: sum over the 8 lane-rows sharing this (l&3) ----
    lsum0 += __shfl_xor_sync(0xffffffffu, lsum0, 4);
    lsum0 += __shfl_xor_sync(0xffffffffu, lsum0, 8);
    lsum0 += __shfl_xor_sync(0xffffffffu, lsum0, 16);
    lsum1 += __shfl_xor_sync(0xffffffffu, lsum1, 4);
    lsum1 += __shfl_xor_sync(0xffffffffu, lsum1, 8);
    lsum1 += __shfl_xor_sync(0xffffffffu, lsum1, 16);
    float li0 = 1.f / lsum0;
    float li1 = 1.f / lsum1;

    // ---- epilogue from D fragments ----
    float gam = gamma[0];
    int q0 = qa;
#pragma unroll
    for (int ct = 0; ct < 4; ct++) {
        int c0 = ct * 16 + (lane >> 2);
        size_t base0 = ((size_t)b * CC + c0) * NN + (size_t)qt * 64 + q0;
        float2 x0 = *(const float2*)(x + base0);
        float2 r0;
        r0.x = gam * acc[ct][0] * li0 + x0.x;
        r0.y = gam * acc[ct][1] * li1 + x0.y;
        *(float2*)(out + base0) = r0;

        size_t base1 = base0 + (size_t)8 * NN;
        float2 x1 = *(const float2*)(x + base1);
        float2 r1;
        r1.x = gam * acc[ct][2] * li0 + x1.x;
        r1.y = gam * acc[ct][3] * li1 + x1.y;
        *(float2*)(out + base1) = r1;
    }
}

// ===========================================================================
extern "C" void kernel_launch(void* const* d_in, const int* in_sizes, int n_in,
                              void* d_out, int out_size) {
    const float* x     = (const float*)d_in[0];
    const float* Wq    = (const float*)d_in[1];
    const float* bq    = (const float*)d_in[2];
    const float* Wk    = (const float*)d_in[3];
    const float* bk    = (const float*)d_in[4];
    const float* Wv    = (const float*)d_in[5];
    const float* bv    = (const float*)d_in[6];
    const float* gamma = (const float*)d_in[7];
    float* out = (float*)d_out;

    prep_kernel<<<3 + (BB * NN) / 256, 256>>>(x, Wq, Wk, Wv);
    attn_kernel<<<dim3(NN / 64, BB), 256>>>(x, bq, bk, bv, gamma, out);
}

// round 12
// speedup vs baseline: 1.8191x; 1.0440x over previous
#include <cuda_runtime.h>
#include <cuda_fp16.h>
#include <math.h>
#include <stdint.h>

// Problem constants
#define NN 9216      // H*W = 96*96
#define CC 64        // channels
#define C8 8         // C/8
#define BB 2         // batch
#define KT 32        // key tile
#define NT (NN / KT) // 288 tiles
#define NTL 576      // NN/16 f-tiles per batch
#define SHIFT 9.70406053f   // 14*ln2: P scaled by 2^14 (cancels in O/l)

// -------- scratch (static device globals: no runtime allocation) ----------
__device__ float    d_invsig[3];                // 1/sigma for Wq, Wk, Wv
__device__ float    d_ft[BB * NTL * 128];       // f~ tiles [tile][d][k-ilv]
__device__ float    d_g[BB * NN * C8];          // raw queries g~ = Wk x
__device__ uint32_t d_h16[BB * NN * 32];        // raw h~ fp16 pairs [n][c]
__device__ float    d_fmax2[144];               // per-prep-block max ||f~||^2

// ---------------- helpers -----------------
__device__ __forceinline__ uint32_t to_tf32(float x) {
    uint32_t u;
    asm("cvt.rna.tf32.f32 %0, %1;" : "=r"(u) : "f"(x));
    return u;
}
__device__ __forceinline__ uint32_t pack_f16(float hi, float lo) {
    uint32_t r;
    asm("cvt.rn.f16x2.f32 %0, %1, %2;" : "=r"(r) : "f"(hi), "f"(lo));
    return r;
}
__device__ __forceinline__ uint32_t movm(uint32_t s) {
    uint32_t d;
    asm("movmatrix.sync.aligned.m8n8.trans.b16 %0, %1;" : "=r"(d) : "r"(s));
    return d;
}
__device__ __forceinline__ void ldsm4t(uint32_t& a0, uint32_t& a1,
                                       uint32_t& a2, uint32_t& a3, uint32_t addr) {
    asm volatile("ldmatrix.sync.aligned.m8n8.x4.trans.shared.b16 {%0,%1,%2,%3}, [%4];"
                 : "=r"(a0), "=r"(a1), "=r"(a2), "=r"(a3) : "r"(addr));
}
__device__ __forceinline__ void mma8(float* d,
        uint32_t a0, uint32_t a1, uint32_t a2, uint32_t a3,
        uint32_t b0, uint32_t b1) {
    asm volatile(
        "mma.sync.aligned.m16n8k8.row.col.f32.tf32.tf32.f32 "
        "{%0,%1,%2,%3},{%4,%5,%6,%7},{%8,%9},{%0,%1,%2,%3};"
        : "+f"(d[0]), "+f"(d[1]), "+f"(d[2]), "+f"(d[3])
        : "r"(a0), "r"(a1), "r"(a2), "r"(a3), "r"(b0), "r"(b1));
}
__device__ __forceinline__ void mma16h(float* d,
        uint32_t a0, uint32_t a1, uint32_t a2, uint32_t a3,
        uint32_t b0, uint32_t b1) {
    asm volatile(
        "mma.sync.aligned.m16n8k16.row.col.f32.f16.f16.f32 "
        "{%0,%1,%2,%3},{%4,%5,%6,%7},{%8,%9},{%0,%1,%2,%3};"
        : "+f"(d[0]), "+f"(d[1]), "+f"(d[2]), "+f"(d[3])
        : "r"(a0), "r"(a1), "r"(a2), "r"(a3), "r"(b0), "r"(b1));
}
__device__ __forceinline__ uint32_t smem_u32(const void* p) {
    uint32_t a;
    asm("{ .reg .u64 t; cvta.to.shared.u64 t, %1; cvt.u32.u64 %0, t; }"
        : "=r"(a) : "l"(p));
    return a;
}
__device__ __forceinline__ void cpasync16(uint32_t dst, const void* src) {
    asm volatile("cp.async.ca.shared.global [%0], [%1], 16;"
                 :: "r"(dst), "l"(src));
}
#define CP_COMMIT() asm volatile("cp.async.commit_group;" ::: "memory")

// ===========================================================================
// K1 (merged, 128 threads): blocks 0-2 spectral norm; blocks 3-146 raw
// projections (128 n-columns each -> 147 blocks = one full wave).
// ===========================================================================
#define SQ_ITERS 4
#define PW_ITERS 16

__global__ void __launch_bounds__(128) prep_kernel(
        const float* __restrict__ x,
        const float* __restrict__ Wq,
        const float* __restrict__ Wk,
        const float* __restrict__ Wv) {
    __shared__ float shb[8448];
    __shared__ float part[4];
    __shared__ float scal;
    int t = threadIdx.x;

    if (blockIdx.x < 3) {
        int mat = blockIdx.x;
        const float* W = (mat == 0) ? Wq : (mat == 1) ? Wk : Wv;
        int dim = (mat == 2) ? 64 : 8;
        float* Ga = shb;                 // 64*65
        float* Gb = shb + 4160;          // 64*65 (also W staging)
        float* vv = shb + 8320;          // 64

        for (int i = t; i < dim * 64; i += 128)
            Gb[(i >> 6) * 65 + (i & 63)] = W[i];
        __syncthreads();

        if (dim == 64) {
            int r = t >> 1, c0 = (t & 1) << 5;
            float rr[64];
#pragma unroll
            for (int j = 0; j < 64; j++) rr[j] = Gb[r * 65 + j];
            float acc[32];
#pragma unroll
            for (int cc = 0; cc < 32; cc++) acc[cc] = 0.f;
            for (int j = 0; j < 64; j++)
#pragma unroll
                for (int cc = 0; cc < 32; cc++)
                    acc[cc] += rr[j] * Gb[(c0 + cc) * 65 + j];
#pragma unroll
            for (int cc = 0; cc < 32; cc++) Ga[r * 65 + c0 + cc] = acc[cc];
        } else if (t < 64) {
            int r = t >> 3, c = t & 7;
            float s = 0.f;
            for (int j = 0; j < 64; j++) s += Gb[r * 65 + j] * Gb[c * 65 + j];
            Ga[r * 65 + c] = s;
        }
        __syncthreads();

        float logl = 0.f, pw = 1.f;
        float* src = Ga;
        float* dst = Gb;
        for (int it = 0; it < SQ_ITERS; it++) {
            float ss = 0.f;
            for (int e = t; e < dim * dim; e += 128) {
                float v = src[(e / dim) * 65 + (e % dim)];
                ss += v * v;
            }
#pragma unroll
            for (int o = 16; o > 0; o >>= 1)
                ss += __shfl_xor_sync(0xffffffffu, ss, o);
            if ((t & 31) == 0) part[t >> 5] = ss;
            __syncthreads();
            float tot = part[0] + part[1] + part[2] + part[3];
            float fro = sqrtf(tot);
            float inv2 = 1.f / tot;
            logl += log2f(fro) * pw;
            pw *= 0.5f;

            if (dim == 64) {
                int r = t >> 1, c0 = (t & 1) << 5;
                float rr[64];
#pragma unroll
                for (int j = 0; j < 64; j++) rr[j] = src[r * 65 + j];
                float acc[32];
#pragma unroll
                for (int cc = 0; cc < 32; cc++) acc[cc] = 0.f;
                for (int j = 0; j < 64; j++)
#pragma unroll
                    for (int cc = 0; cc < 32; cc++)
                        acc[cc] += rr[j] * src[j * 65 + c0 + cc];
#pragma unroll
                for (int cc = 0; cc < 32; cc++)
                    dst[r * 65 + c0 + cc] = acc[cc] * inv2;
            } else if (t < 64) {
                int r = t >> 3, c = t & 7;
                float s = 0.f;
#pragma unroll
                for (int j = 0; j < 8; j++) s += src[r * 65 + j] * src[j * 65 + c];
                dst[r * 65 + c] = s * inv2;
            }
            __syncthreads();
            float* tmp = src; src = dst; dst = tmp;
        }

        if (t < 64) vv[t] = 1.f;
        __syncthreads();
        float lam = 1.f;
        for (int it = 0; it < PW_ITERS; it++) {
            float w = 0.f;
            if (t < dim) {
                const float* gr = src + t * 65;
                for (int j = 0; j < dim; j++) w += gr[j] * vv[j];
            }
            float sq = w * w;
#pragma unroll
            for (int o = 16; o > 0; o >>= 1)
                sq += __shfl_xor_sync(0xffffffffu, sq, o);
            if ((t & 31) == 0) part[t >> 5] = sq;
            __syncthreads();
            if (t == 0) scal = sqrtf(part[0] + part[1]);
            __syncthreads();
            lam = scal;
            if (t < dim) vv[t] = w / lam;
            __syncthreads();
        }
        if (t == 0) {
            float l0 = log2f(lam) * pw + logl;
            d_invsig[mat] = exp2f(-0.5f * l0);
        }
    } else {
        float* wq = shb;            // 512
        float* wk = shb + 512;      // 512
        float* wv = shb + 1024;     // 4096

        for (int i = t; i < 512; i += 128) { wq[i] = Wq[i]; wk[i] = Wk[i]; }
        for (int i = t; i < 4096; i += 128) wv[i] = Wv[i];
        __syncthreads();

        int gid = (blockIdx.x - 3) * 128 + t;       // 0 .. 18431
        int b = gid / NN, n = gid % NN;

        float fa[8] = {0.f}, ga[8] = {0.f}, ha[64] = {0.f};
        const float* xp = x + (size_t)b * CC * NN + n;
        for (int c = 0; c < 64; c++) {
            float xc = xp[(size_t)c * NN];
#pragma unroll
            for (int o = 0; o < 8; o++) {
                fa[o] += wq[o * 64 + c] * xc;
                ga[o] += wk[o * 64 + c] * xc;
            }
#pragma unroll
            for (int o = 0; o < 64; o++) ha[o] += wv[o * 64 + c] * xc;
        }

        // f: transposed tile layout [tile][d][2*(k&7)+((k>>3)&1)]
        {
            int tl = n >> 4, kk = n & 15;
            size_t fb = ((size_t)b * NTL + tl) * 128
                      + 2 * (kk & 7) + ((kk >> 3) & 1);
#pragma unroll
            for (int o = 0; o < 8; o++) d_ft[fb + o * 16] = fa[o];
        }
        // g
        size_t b8 = ((size_t)b * NN + n) * 8;
#pragma unroll
        for (int o = 0; o < 8; o++) d_g[b8 + o] = ga[o];
        // h: raw fp16 pairs [n][c]
        {
            uint32_t hw[32];
#pragma unroll
            for (int i = 0; i < 32; i++)
                hw[i] = pack_f16(ha[2 * i + 1], ha[2 * i]);
            uint4* hp = (uint4*)(d_h16 + ((size_t)b * NN + n) * 32);
#pragma unroll
            for (int j = 0; j < 8; j++)
                hp[j] = make_uint4(hw[4 * j], hw[4 * j + 1],
                                   hw[4 * j + 2], hw[4 * j + 3]);
        }

        // block max of ||f~||^2
        float n2 = 0.f;
#pragma unroll
        for (int o = 0; o < 8; o++) n2 += fa[o] * fa[o];
#pragma unroll
        for (int o = 16; o > 0; o >>= 1)
            n2 = fmaxf(n2, __shfl_xor_sync(0xffffffffu, n2, o));
        if ((t & 31) == 0) part[t >> 5] = n2;
        __syncthreads();
        if (t == 0) {
            float m = fmaxf(fmaxf(part[0], part[1]), fmaxf(part[2], part[3]));
            d_fmax2[blockIdx.x - 3] = m;
        }
    }
}

// ===========================================================================
// K2: single-pass flash attention, fully tensor-core, cp.async H pipeline.
//   O = Sum p*(iv*h~+bv) = iv*(Sum p h~) + bv*l  -> PV runs on RAW fp16 h~.
//   Scores: tf32 3-term on coalesced d_ft fragments; movmatrix -> P B-frags.
//   H: cp.async 16B/thread into XOR-swizzled [k][c] tile (3-stage ring),
//      ldmatrix.x4.trans A-frags, fp16 single-plane P (error-averaging OK).
// 8 warps: warp w owns q-cols [8w, 8w+8), all 64 c rows.
// ===========================================================================
__global__ void __launch_bounds__(256, 2) attn_kernel(
        const float* __restrict__ x,
        const float* __restrict__ bq,
        const float* __restrict__ bk,
        const float* __restrict__ bv,
        const float* __restrict__ gamma,
        float* __restrict__ out) {
    __shared__ __align__(16) uint32_t hbuf[3][1024];   // 3 x 4KB fp16 H tiles
    __shared__ float g_sh[64 * 9];
    __shared__ float red8[8];

    int t    = threadIdx.x;
    int wid  = t >> 5;
    int lane = t & 31;
    int b    = blockIdx.y;
    int qt   = blockIdx.x;

    float iq = d_invsig[0], ik = d_invsig[1], iv = d_invsig[2];

    // stage g tile (scaled + bias)
    const float* gp = d_g + ((size_t)b * NN + qt * 64) * 8;
    for (int i = t; i < 512; i += 256)
        g_sh[(i >> 3) * 9 + (i & 7)] = ik * gp[i] + __ldg(bk + (i & 7));

    // Fmax^2 reduction (144 values)
    {
        float fm = (t < 144) ? d_fmax2[t] : 0.f;
#pragma unroll
        for (int o = 16; o > 0; o >>= 1)
            fm = fmaxf(fm, __shfl_xor_sync(0xffffffffu, fm, o));
        if (lane == 0) red8[wid] = fm;
    }

    // H staging role + prologue cp.async for tiles 0,1
    int srow = t >> 3, sj = t & 7;
    const char* hsrc = (const char*)d_h16
                     + ((size_t)(b * NN + srow)) * 128 + sj * 16;
    uint32_t hb0  = smem_u32(&hbuf[0][0]);
    uint32_t sdst = hb0 + srow * 128 + ((sj ^ (srow & 7)) << 4);
    cpasync16(sdst, hsrc);
    CP_COMMIT();
    cpasync16(sdst + 4096, hsrc + 4096);
    CP_COMMIT();

    __syncthreads();
    float Fmax;
    {
        float fm = red8[0];
#pragma unroll
        for (int i = 1; i < 8; i++) fm = fmaxf(fm, red8[i]);
        Fmax = sqrtf(fm);
    }

    // G B-fragments (tf32 hi/lo): b0=(d=l&3, q=l>>2), b1=d+4
    uint32_t Ghi0, Ghi1, Glo0, Glo1;
    {
        int qn = 8 * wid + (lane >> 2);
        float g0 = g_sh[qn * 9 + (lane & 3)];
        float g1 = g_sh[qn * 9 + (lane & 3) + 4];
        Ghi0 = to_tf32(g0); Glo0 = to_tf32(g0 - __uint_as_float(Ghi0));
        Ghi1 = to_tf32(g1); Glo1 = to_tf32(g1 - __uint_as_float(Ghi1));
    }

    // exponent constants for this lane's two q columns (qa, qa+1)
    int qa = 8 * wid + 2 * (lane & 3);
    float cqm0, cqm1;
    {
        float n20 = 0.f, n21 = 0.f;
#pragma unroll
        for (int d = 0; d < 8; d++) {
            float v0 = g_sh[qa * 9 + d];
            float v1 = g_sh[(qa + 1) * 9 + d];
            n20 += v0 * v0;
            n21 += v1 * v1;
        }
        cqm0 = SHIFT - iq * Fmax * sqrtf(n20);
        cqm1 = SHIFT - iq * Fmax * sqrtf(n21);
    }

    // ldsm.trans A-frag static offsets
    int lm = lane & 7, g1b = (lane >> 3) & 1, g2b = lane >> 4;
    uint32_t offA[4][2];
#pragma unroll
    for (int ct = 0; ct < 4; ct++)
#pragma unroll
        for (int ks = 0; ks < 2; ks++)
            offA[ct][ks] = hb0 + (ks * 16 + g2b * 8 + lm) * 128
                         + (((2 * ct + g1b) ^ lm) << 4);

    float acc[4][4];
#pragma unroll
    for (int i = 0; i < 4; i++)
#pragma unroll
        for (int j = 0; j < 4; j++) acc[i][j] = 0.f;
    float lsum0 = 0.f, lsum1 = 0.f;

    const float* fbase = d_ft + (size_t)b * NTL * 128;
    int foff = (lane & 3) * 16 + 2 * (lane >> 2);

    for (int kt = 0; kt < NT; kt++) {
        int cur = kt % 3;

        if (kt < NT - 1)
            asm volatile("cp.async.wait_group 1;" ::: "memory");
        else
            asm volatile("cp.async.wait_group 0;" ::: "memory");
        __syncthreads();

        if (kt + 2 < NT) {
            cpasync16(sdst + ((kt + 2) % 3) * 4096,
                      hsrc + (size_t)(kt + 2) * 4096);
            CP_COMMIT();
        }

        // ---- scores on tensor cores -> P B-frags (registers only) ----
        uint32_t Bh[2][2];
        const float* fpb = fbase + (size_t)(kt * 2) * 128;
#pragma unroll
        for (int mt = 0; mt < 2; mt++) {
            const float* fp = fpb + mt * 128;
            float2 A01 = *(const float2*)(fp + foff);
            float2 A23 = *(const float2*)(fp + foff + 64);
            uint32_t Ah0 = to_tf32(A01.x), Ah1 = to_tf32(A01.y);
            uint32_t Ah2 = to_tf32(A23.x), Ah3 = to_tf32(A23.y);
            uint32_t Al0 = to_tf32(A01.x - __uint_as_float(Ah0));
            uint32_t Al1 = to_tf32(A01.y - __uint_as_float(Ah1));
            uint32_t Al2 = to_tf32(A23.x - __uint_as_float(Ah2));
            uint32_t Al3 = to_tf32(A23.y - __uint_as_float(Ah3));

            float D[4] = {0.f, 0.f, 0.f, 0.f};
            mma8(D, Ah0, Ah1, Ah2, Ah3, Ghi0, Ghi1);
            mma8(D, Ah0, Ah1, Ah2, Ah3, Glo0, Glo1);
            mma8(D, Al0, Al1, Al2, Al3, Ghi0, Ghi1);

            float p0 = __expf(fmaf(iq, D[0], cqm0));
            float p1 = __expf(fmaf(iq, D[1], cqm1));
            float p2 = __expf(fmaf(iq, D[2], cqm0));
            float p3 = __expf(fmaf(iq, D[3], cqm1));
            lsum0 += p0 + p2;
            lsum1 += p1 + p3;

            Bh[mt][0] = movm(pack_f16(p1, p0));   // keys mt*16+0..7
            Bh[mt][1] = movm(pack_f16(p3, p2));   // keys mt*16+8..15
        }

        // ---- PV: O += H~ * P ----
        uint32_t bufo = cur * 4096;
#pragma unroll
        for (int ct = 0; ct < 4; ct++) {
#pragma unroll
            for (int ks = 0; ks < 2; ks++) {
                uint32_t a0, a1, a2, a3;
                ldsm4t(a0, a1, a2, a3, offA[ct][ks] + bufo);
                mma16h(acc[ct], a0, a1, a2, a3, Bh[ks][0], Bh[ks][1]);
            }
        }
    }

    // ---- denominator: sum over the 8 lane-rows sharing (l&3) ----
    lsum0 += __shfl_xor_sync(0xffffffffu, lsum0, 4);
    lsum0 += __shfl_xor_sync(0xffffffffu, lsum0, 8);
    lsum0 += __shfl_xor_sync(0xffffffffu, lsum0, 16);
    lsum1 += __shfl_xor_sync(0xffffffffu, lsum1, 4);
    lsum1 += __shfl_xor_sync(0xffffffffu, lsum1, 8);
    lsum1 += __shfl_xor_sync(0xffffffffu, lsum1, 16);
    float li0 = 1.f / lsum0;
    float li1 = 1.f / lsum1;

    // ---- epilogue: out = gam*iv*O~/l + gam*bv + x ----
    float gam = gamma[0];
    float giv = gam * iv;
#pragma unroll
    for (int ct = 0; ct < 4; ct++) {
        int c0 = ct * 16 + (lane >> 2);
        float gb0 = gam * __ldg(bv + c0);
        float gb1 = gam * __ldg(bv + c0 + 8);

        size_t base0 = ((size_t)b * CC + c0) * NN + (size_t)qt * 64 + qa;
        float2 x0 = *(const float2*)(x + base0);
        float2 r0;
        r0.x = giv * acc[ct][0] * li0 + gb0 + x0.x;
        r0.y = giv * acc[ct][1] * li1 + gb0 + x0.y;
        *(float2*)(out + base0) = r0;

        size_t base1 = base0 + (size_t)8 * NN;
        float2 x1 = *(const float2*)(x + base1);
        float2 r1;
        r1.x = giv * acc[ct][2] * li0 + gb1 + x1.x;
        r1.y = giv * acc[ct][3] * li1 + gb1 + x1.y;
        *(float2*)(out + base1) = r1;
    }
}

// ===========================================================================
extern "C" void kernel_launch(void* const* d_in, const int* in_sizes, int n_in,
                              void* d_out, int out_size) {
    const float* x     = (const float*)d_in[0];
    const float* Wq    = (const float*)d_in[1];
    const float* bq    = (const float*)d_in[2];
    const float* Wk    = (const float*)d_in[3];
    const float* bk    = (const float*)d_in[4];
    const float* Wv    = (const float*)d_in[5];
    const float* bv    = (const float*)d_in[6];
    const float* gamma = (const float*)d_in[7];
    float* out = (float*)d_out;
    (void)bq;

    prep_kernel<<<3 + (BB * NN) / 128, 128>>>(x, Wq, Wk, Wv);
    attn_kernel<<<dim3(NN / 64, BB), 256>>>(x, bq, bk, bv, gamma, out);
}

// round 13
// speedup vs baseline: 1.8446x; 1.0141x over previous
#include <cuda_runtime.h>
#include <cuda_fp16.h>
#include <math.h>
#include <stdint.h>

// Problem constants
#define NN 9216      // H*W = 96*96
#define CC 64        // channels
#define C8 8         // C/8
#define BB 2         // batch
#define KT 32        // key tile
#define NT (NN / KT) // 288 tiles
#define NTL 576      // NN/16 f-tiles per batch
#define SHIFT 9.70406053f   // 14*ln2: P scaled by 2^14 (cancels in O/l)
#define LOG2E 1.44269504f

// -------- scratch (static device globals: no runtime allocation) ----------
__device__ float    d_invsig[3];                // 1/sigma for Wq, Wk, Wv
__device__ uint32_t d_f16[BB * NTL * 32 * 4];   // f~ hi/lo fp16 A-fragments
__device__ float    d_g[BB * NN * C8];          // raw queries g~ = Wk x
__device__ uint32_t d_h16[BB * NN * 32];        // raw h~ fp16 pairs [n][c]
__device__ float    d_fmax2[144];               // per-prep-block max ||f~||^2

// ---------------- helpers -----------------
__device__ __forceinline__ uint32_t pack_f16(float hi, float lo) {
    uint32_t r;
    asm("cvt.rn.f16x2.f32 %0, %1, %2;" : "=r"(r) : "f"(hi), "f"(lo));
    return r;
}
__device__ __forceinline__ uint32_t movm(uint32_t s) {
    uint32_t d;
    asm("movmatrix.sync.aligned.m8n8.trans.b16 %0, %1;" : "=r"(d) : "r"(s));
    return d;
}
__device__ __forceinline__ void ldsm4t(uint32_t& a0, uint32_t& a1,
                                       uint32_t& a2, uint32_t& a3, uint32_t addr) {
    asm volatile("ldmatrix.sync.aligned.m8n8.x4.trans.shared.b16 {%0,%1,%2,%3}, [%4];"
                 : "=r"(a0), "=r"(a1), "=r"(a2), "=r"(a3) : "r"(addr));
}
__device__ __forceinline__ void mma16h(float* d,
        uint32_t a0, uint32_t a1, uint32_t a2, uint32_t a3,
        uint32_t b0, uint32_t b1) {
    asm volatile(
        "mma.sync.aligned.m16n8k16.row.col.f32.f16.f16.f32 "
        "{%0,%1,%2,%3},{%4,%5,%6,%7},{%8,%9},{%0,%1,%2,%3};"
        : "+f"(d[0]), "+f"(d[1]), "+f"(d[2]), "+f"(d[3])
        : "r"(a0), "r"(a1), "r"(a2), "r"(a3), "r"(b0), "r"(b1));
}
__device__ __forceinline__ uint32_t smem_u32(const void* p) {
    uint32_t a;
    asm("{ .reg .u64 t; cvta.to.shared.u64 t, %1; cvt.u32.u64 %0, t; }"
        : "=r"(a) : "l"(p));
    return a;
}
__device__ __forceinline__ void cpasync16(uint32_t dst, const void* src) {
    asm volatile("cp.async.ca.shared.global [%0], [%1], 16;"
                 :: "r"(dst), "l"(src));
}
#define CP_COMMIT() asm volatile("cp.async.commit_group;" ::: "memory")

// ===========================================================================
// K1 (merged, 128 threads): blocks 0-2 spectral norm; blocks 3-146 raw
// projections (128 n-columns each -> 147 blocks = one full wave).
// ===========================================================================
#define SQ_ITERS 4
#define PW_ITERS 16

__global__ void __launch_bounds__(128) prep_kernel(
        const float* __restrict__ x,
        const float* __restrict__ Wq,
        const float* __restrict__ Wk,
        const float* __restrict__ Wv) {
    __shared__ float shb[8448];
    __shared__ float part[4];
    __shared__ float scal;
    int t = threadIdx.x;

    if (blockIdx.x < 3) {
        int mat = blockIdx.x;
        const float* W = (mat == 0) ? Wq : (mat == 1) ? Wk : Wv;
        int dim = (mat == 2) ? 64 : 8;
        float* Ga = shb;                 // 64*65
        float* Gb = shb + 4160;          // 64*65 (also W staging)
        float* vv = shb + 8320;          // 64

        for (int i = t; i < dim * 64; i += 128)
            Gb[(i >> 6) * 65 + (i & 63)] = W[i];
        __syncthreads();

        if (dim == 64) {
            int r = t >> 1, c0 = (t & 1) << 5;
            float rr[64];
#pragma unroll
            for (int j = 0; j < 64; j++) rr[j] = Gb[r * 65 + j];
            float acc[32];
#pragma unroll
            for (int cc = 0; cc < 32; cc++) acc[cc] = 0.f;
            for (int j = 0; j < 64; j++)
#pragma unroll
                for (int cc = 0; cc < 32; cc++)
                    acc[cc] += rr[j] * Gb[(c0 + cc) * 65 + j];
#pragma unroll
            for (int cc = 0; cc < 32; cc++) Ga[r * 65 + c0 + cc] = acc[cc];
        } else if (t < 64) {
            int r = t >> 3, c = t & 7;
            float s = 0.f;
            for (int j = 0; j < 64; j++) s += Gb[r * 65 + j] * Gb[c * 65 + j];
            Ga[r * 65 + c] = s;
        }
        __syncthreads();

        float logl = 0.f, pw = 1.f;
        float* src = Ga;
        float* dst = Gb;
        for (int it = 0; it < SQ_ITERS; it++) {
            float ss = 0.f;
            for (int e = t; e < dim * dim; e += 128) {
                float v = src[(e / dim) * 65 + (e % dim)];
                ss += v * v;
            }
#pragma unroll
            for (int o = 16; o > 0; o >>= 1)
                ss += __shfl_xor_sync(0xffffffffu, ss, o);
            if ((t & 31) == 0) part[t >> 5] = ss;
            __syncthreads();
            float tot = part[0] + part[1] + part[2] + part[3];
            float fro = sqrtf(tot);
            float inv2 = 1.f / tot;
            logl += log2f(fro) * pw;
            pw *= 0.5f;

            if (dim == 64) {
                int r = t >> 1, c0 = (t & 1) << 5;
                float rr[64];
#pragma unroll
                for (int j = 0; j < 64; j++) rr[j] = src[r * 65 + j];
                float acc[32];
#pragma unroll
                for (int cc = 0; cc < 32; cc++) acc[cc] = 0.f;
                for (int j = 0; j < 64; j++)
#pragma unroll
                    for (int cc = 0; cc < 32; cc++)
                        acc[cc] += rr[j] * src[j * 65 + c0 + cc];
#pragma unroll
                for (int cc = 0; cc < 32; cc++)
                    dst[r * 65 + c0 + cc] = acc[cc] * inv2;
            } else if (t < 64) {
                int r = t >> 3, c = t & 7;
                float s = 0.f;
#pragma unroll
                for (int j = 0; j < 8; j++) s += src[r * 65 + j] * src[j * 65 + c];
                dst[r * 65 + c] = s * inv2;
            }
            __syncthreads();
            float* tmp = src; src = dst; dst = tmp;
        }

        if (t < 64) vv[t] = 1.f;
        __syncthreads();
        float lam = 1.f;
        for (int it = 0; it < PW_ITERS; it++) {
            float w = 0.f;
            if (t < dim) {
                const float* gr = src + t * 65;
                for (int j = 0; j < dim; j++) w += gr[j] * vv[j];
            }
            float sq = w * w;
#pragma unroll
            for (int o = 16; o > 0; o >>= 1)
                sq += __shfl_xor_sync(0xffffffffu, sq, o);
            if ((t & 31) == 0) part[t >> 5] = sq;
            __syncthreads();
            if (t == 0) scal = sqrtf(part[0] + part[1]);
            __syncthreads();
            lam = scal;
            if (t < dim) vv[t] = w / lam;
            __syncthreads();
        }
        if (t == 0) {
            float l0 = log2f(lam) * pw + logl;
            d_invsig[mat] = exp2f(-0.5f * l0);
        }
    } else {
        float* wq = shb;            // 512
        float* wk = shb + 512;      // 512
        float* wv = shb + 1024;     // 4096

        for (int i = t; i < 512; i += 128) { wq[i] = Wq[i]; wk[i] = Wk[i]; }
        for (int i = t; i < 4096; i += 128) wv[i] = Wv[i];
        __syncthreads();

        int gid = (blockIdx.x - 3) * 128 + t;       // 0 .. 18431
        int b = gid / NN, n = gid % NN;

        float fa[8] = {0.f}, ga[8] = {0.f}, ha[64] = {0.f};
        const float* xp = x + (size_t)b * CC * NN + n;
        for (int c = 0; c < 64; c++) {
            float xc = xp[(size_t)c * NN];
#pragma unroll
            for (int o = 0; o < 8; o++) {
                fa[o] += wq[o * 64 + c] * xc;
                ga[o] += wk[o * 64 + c] * xc;
            }
#pragma unroll
            for (int o = 0; o < 64; o++) ha[o] += wv[o * 64 + c] * xc;
        }

        // f: fp16 hi/lo pairs in m16n8k16 A-fragment layout.
        // key n: tile=n>>4, r=n&15; lanes 4*(r&7)+c hold channel pair (2c,2c+1);
        // reg = (r>>3) for hi plane, 2+(r>>3) for lo plane.
        {
            int tl = n >> 4, r = n & 15;
            uint32_t* fb = d_f16 + ((size_t)(b * NTL + tl) * 32
                                    + 4 * (r & 7)) * 4 + ((r >> 3) & 1);
#pragma unroll
            for (int c = 0; c < 4; c++) {
                __half h0 = __float2half_rn(fa[2 * c]);
                __half h1 = __float2half_rn(fa[2 * c + 1]);
                float l0 = fa[2 * c]     - __half2float(h0);
                float l1 = fa[2 * c + 1] - __half2float(h1);
                uint32_t hi = ((uint32_t)__half_as_ushort(h1) << 16)
                            | __half_as_ushort(h0);
                fb[c * 4]     = hi;
                fb[c * 4 + 2] = pack_f16(l1, l0);
            }
        }
        // g
        size_t b8 = ((size_t)b * NN + n) * 8;
#pragma unroll
        for (int o = 0; o < 8; o++) d_g[b8 + o] = ga[o];
        // h: raw fp16 pairs [n][c]
        {
            uint32_t hw[32];
#pragma unroll
            for (int i = 0; i < 32; i++)
                hw[i] = pack_f16(ha[2 * i + 1], ha[2 * i]);
            uint4* hp = (uint4*)(d_h16 + ((size_t)b * NN + n) * 32);
#pragma unroll
            for (int j = 0; j < 8; j++)
                hp[j] = make_uint4(hw[4 * j], hw[4 * j + 1],
                                   hw[4 * j + 2], hw[4 * j + 3]);
        }

        // block max of ||f~||^2
        float n2 = 0.f;
#pragma unroll
        for (int o = 0; o < 8; o++) n2 += fa[o] * fa[o];
#pragma unroll
        for (int o = 16; o > 0; o >>= 1)
            n2 = fmaxf(n2, __shfl_xor_sync(0xffffffffu, n2, o));
        if ((t & 31) == 0) part[t >> 5] = n2;
        __syncthreads();
        if (t == 0) {
            float m = fmaxf(fmaxf(part[0], part[1]), fmaxf(part[2], part[3]));
            d_fmax2[blockIdx.x - 3] = m;
        }
    }
}

// ===========================================================================
// K2: single-pass flash attention, fully tensor-core.
//   Scores: fp16 m16n8k16 on pre-split f fragments (LDG.128 direct to mma);
//           k16 packs [f_hi|f_lo]; B = [g_hi|g_hi] then [g_lo|g_lo] -> full
//           product to ~2^-22. No conversions in the hot loop.
//   P: exp2 in D-frags; movmatrix -> PV B-frags (single fp16 plane).
//   PV: raw fp16 h~ via cp.async ring + ldmatrix.trans; O folds iv/bv after.
// 8 warps: warp w owns q-cols [8w, 8w+8), all 64 c rows.
// ===========================================================================
__global__ void __launch_bounds__(256, 2) attn_kernel(
        const float* __restrict__ x,
        const float* __restrict__ bq,
        const float* __restrict__ bk,
        const float* __restrict__ bv,
        const float* __restrict__ gamma,
        float* __restrict__ out) {
    __shared__ __align__(16) uint32_t hbuf[3][1024];   // 3 x 4KB fp16 H tiles
    __shared__ float g_sh[64 * 9];
    __shared__ float red8[8];

    int t    = threadIdx.x;
    int wid  = t >> 5;
    int lane = t & 31;
    int b    = blockIdx.y;
    int qt   = blockIdx.x;

    float iq = d_invsig[0], ik = d_invsig[1], iv = d_invsig[2];

    // stage g tile (scaled + bias)
    const float* gp = d_g + ((size_t)b * NN + qt * 64) * 8;
    for (int i = t; i < 512; i += 256)
        g_sh[(i >> 3) * 9 + (i & 7)] = ik * gp[i] + __ldg(bk + (i & 7));

    // Fmax^2 reduction (144 values)
    {
        float fm = (t < 144) ? d_fmax2[t] : 0.f;
#pragma unroll
        for (int o = 16; o > 0; o >>= 1)
            fm = fmaxf(fm, __shfl_xor_sync(0xffffffffu, fm, o));
        if (lane == 0) red8[wid] = fm;
    }

    // H staging role + prologue cp.async for tiles 0,1
    int srow = t >> 3, sj = t & 7;
    const char* hsrc = (const char*)d_h16
                     + ((size_t)(b * NN + srow)) * 128 + sj * 16;
    uint32_t hb0  = smem_u32(&hbuf[0][0]);
    uint32_t sdst = hb0 + srow * 128 + ((sj ^ (srow & 7)) << 4);
    cpasync16(sdst, hsrc);
    CP_COMMIT();
    cpasync16(sdst + 4096, hsrc + 4096);
    CP_COMMIT();

    __syncthreads();
    float Fmax;
    {
        float fm = red8[0];
#pragma unroll
        for (int i = 1; i < 8; i++) fm = fmaxf(fm, red8[i]);
        Fmax = sqrtf(fm);
    }

    // G B-fragments (fp16 hi/lo): query n=8w+(l>>2), channels 2(l&3),2(l&3)+1
    uint32_t bgh, bgl;
    {
        int qn = 8 * wid + (lane >> 2);
        int d0 = 2 * (lane & 3);
        float g0 = g_sh[qn * 9 + d0];
        float g1 = g_sh[qn * 9 + d0 + 1];
        __half h0 = __float2half_rn(g0);
        __half h1 = __float2half_rn(g1);
        bgh = ((uint32_t)__half_as_ushort(h1) << 16) | __half_as_ushort(h0);
        bgl = pack_f16(g1 - __half2float(h1), g0 - __half2float(h0));
    }

    // exp2 constants for this lane's two q columns (qa, qa+1)
    int qa = 8 * wid + 2 * (lane & 3);
    float iq2 = iq * LOG2E;
    float cq20, cq21;
    {
        float n20 = 0.f, n21 = 0.f;
#pragma unroll
        for (int d = 0; d < 8; d++) {
            float v0 = g_sh[qa * 9 + d];
            float v1 = g_sh[(qa + 1) * 9 + d];
            n20 += v0 * v0;
            n21 += v1 * v1;
        }
        cq20 = (SHIFT - iq * Fmax * sqrtf(n20)) * LOG2E;
        cq21 = (SHIFT - iq * Fmax * sqrtf(n21)) * LOG2E;
    }

    // ldsm.trans A-frag static offsets
    int lm = lane & 7, g1b = (lane >> 3) & 1, g2b = lane >> 4;
    uint32_t offA[4][2];
#pragma unroll
    for (int ct = 0; ct < 4; ct++)
#pragma unroll
        for (int ks = 0; ks < 2; ks++)
            offA[ct][ks] = hb0 + (ks * 16 + g2b * 8 + lm) * 128
                         + (((2 * ct + g1b) ^ lm) << 4);

    float acc[4][4];
#pragma unroll
    for (int i = 0; i < 4; i++)
#pragma unroll
        for (int j = 0; j < 4; j++) acc[i][j] = 0.f;
    float lsum0 = 0.f, lsum1 = 0.f;

    const uint4* fbase = (const uint4*)d_f16 + (size_t)b * NTL * 32 + lane;

    for (int kt = 0; kt < NT; kt++) {
        int cur = kt % 3;

        if (kt < NT - 1)
            asm volatile("cp.async.wait_group 1;" ::: "memory");
        else
            asm volatile("cp.async.wait_group 0;" ::: "memory");
        __syncthreads();

        if (kt + 2 < NT) {
            cpasync16(sdst + ((kt + 2) % 3) * 4096,
                      hsrc + (size_t)(kt + 2) * 4096);
            CP_COMMIT();
        }

        // ---- scores: fp16 mma on pre-split fragments ----
        uint32_t Bh[2][2];
#pragma unroll
        for (int mt = 0; mt < 2; mt++) {
            uint4 Af = __ldg(fbase + (size_t)(kt * 2 + mt) * 32);

            float D[4] = {0.f, 0.f, 0.f, 0.f};
            mma16h(D, Af.x, Af.y, Af.z, Af.w, bgh, bgh);
            mma16h(D, Af.x, Af.y, Af.z, Af.w, bgl, bgl);

            float p0 = exp2f(fmaf(iq2, D[0], cq20));
            float p1 = exp2f(fmaf(iq2, D[1], cq21));
            float p2 = exp2f(fmaf(iq2, D[2], cq20));
            float p3 = exp2f(fmaf(iq2, D[3], cq21));
            lsum0 += p0 + p2;
            lsum1 += p1 + p3;

            Bh[mt][0] = movm(pack_f16(p1, p0));   // keys mt*16+0..7
            Bh[mt][1] = movm(pack_f16(p3, p2));   // keys mt*16+8..15
        }

        // ---- PV: O += H~ * P ----
        uint32_t bufo = cur * 4096;
#pragma unroll
        for (int ct = 0; ct < 4; ct++) {
#pragma unroll
            for (int ks = 0; ks < 2; ks++) {
                uint32_t a0, a1, a2, a3;
                ldsm4t(a0, a1, a2, a3, offA[ct][ks] + bufo);
                mma16h(acc[ct], a0, a1, a2, a3, Bh[ks][0], Bh[ks][1]);
            }
        }
    }

    // ---- denominator: sum over the 8 lane-rows sharing (l&3) ----
    lsum0 += __shfl_xor_sync(0xffffffffu, lsum0, 4);
    lsum0 += __shfl_xor_sync(0xffffffffu, lsum0, 8);
    lsum0 += __shfl_xor_sync(0xffffffffu, lsum0, 16);
    lsum1 += __shfl_xor_sync(0xffffffffu, lsum1, 4);
    lsum1 += __shfl_xor_sync(0xffffffffu, lsum1, 8);
    lsum1 += __shfl_xor_sync(0xffffffffu, lsum1, 16);
    float li0 = 1.f / lsum0;
    float li1 = 1.f / lsum1;

    // ---- epilogue: out = gam*iv*O~/l + gam*bv + x ----
    float gam = gamma[0];
    float giv = gam * iv;
#pragma unroll
    for (int ct = 0; ct < 4; ct++) {
        int c0 = ct * 16 + (lane >> 2);
        float gb0 = gam * __ldg(bv + c0);
        float gb1 = gam * __ldg(bv + c0 + 8);

        size_t base0 = ((size_t)b * CC + c0) * NN + (size_t)qt * 64 + qa;
        float2 x0 = *(const float2*)(x + base0);
        float2 r0;
        r0.x = giv * acc[ct][0] * li0 + gb0 + x0.x;
        r0.y = giv * acc[ct][1] * li1 + gb0 + x0.y;
        *(float2*)(out + base0) = r0;

        size_t base1 = base0 + (size_t)8 * NN;
        float2 x1 = *(const float2*)(x + base1);
        float2 r1;
        r1.x = giv * acc[ct][2] * li0 + gb1 + x1.x;
        r1.y = giv * acc[ct][3] * li1 + gb1 + x1.y;
        *(float2*)(out + base1) = r1;
    }
}

// ===========================================================================
extern "C" void kernel_launch(void* const* d_in, const int* in_sizes, int n_in,
                              void* d_out, int out_size) {
    const float* x     = (const float*)d_in[0];
    const float* Wq    = (const float*)d_in[1];
    const float* bq    = (const float*)d_in[2];
    const float* Wk    = (const float*)d_in[3];
    const float* bk    = (const float*)d_in[4];
    const float* Wv    = (const float*)d_in[5];
    const float* bv    = (const float*)d_in[6];
    const float* gamma = (const float*)d_in[7];
    float* out = (float*)d_out;
    (void)bq;

    prep_kernel<<<3 + (BB * NN) / 128, 128>>>(x, Wq, Wk, Wv);
    attn_kernel<<<dim3(NN / 64, BB), 256>>>(x, bq, bk, bv, gamma, out);
}

// round 14
// speedup vs baseline: 3.7688x; 2.0431x over previous
#include <cuda_runtime.h>
#include <cuda_fp16.h>
#include <math.h>
#include <stdint.h>

// Problem constants
#define NN 9216      // H*W = 96*96
#define CC 64        // channels
#define C8 8         // C/8
#define BB 2         // batch
#define KT 64        // key tile
#define NT (NN / KT) // 144 tiles
#define NTL 576      // NN/16 f-tiles per batch
#define SHIFT 9.70406053f   // 14*ln2: P scaled by 2^14 (cancels in O/l)
#define LOG2E 1.44269504f

// -------- scratch (static device globals: no runtime allocation) ----------
__device__ float    d_invsig[3];                // 1/sigma for Wq, Wk, Wv
__device__ uint32_t d_f16[BB * NTL * 32 * 4];   // f~ hi/lo fp16 A-fragments
__device__ float    d_g[BB * NN * C8];          // raw queries g~ = Wk x
__device__ uint32_t d_h16[BB * NN * 32];        // raw h~ fp16 pairs [n][c]
__device__ float    d_fmax2[72];                // per-prep-block max ||f~||^2

// ---------------- helpers -----------------
__device__ __forceinline__ uint32_t pack_f16(float hi, float lo) {
    uint32_t r;
    asm("cvt.rn.f16x2.f32 %0, %1, %2;" : "=r"(r) : "f"(hi), "f"(lo));
    return r;
}
__device__ __forceinline__ float ex2(float x) {
    float y;
    asm("ex2.approx.f32 %0, %1;" : "=f"(y) : "f"(x));
    return y;
}
__device__ __forceinline__ uint32_t movm(uint32_t s) {
    uint32_t d;
    asm("movmatrix.sync.aligned.m8n8.trans.b16 %0, %1;" : "=r"(d) : "r"(s));
    return d;
}
__device__ __forceinline__ void ldsm4t(uint32_t& a0, uint32_t& a1,
                                       uint32_t& a2, uint32_t& a3, uint32_t addr) {
    asm volatile("ldmatrix.sync.aligned.m8n8.x4.trans.shared.b16 {%0,%1,%2,%3}, [%4];"
                 : "=r"(a0), "=r"(a1), "=r"(a2), "=r"(a3) : "r"(addr));
}
__device__ __forceinline__ void mma16h(float* d,
        uint32_t a0, uint32_t a1, uint32_t a2, uint32_t a3,
        uint32_t b0, uint32_t b1) {
    asm volatile(
        "mma.sync.aligned.m16n8k16.row.col.f32.f16.f16.f32 "
        "{%0,%1,%2,%3},{%4,%5,%6,%7},{%8,%9},{%0,%1,%2,%3};"
        : "+f"(d[0]), "+f"(d[1]), "+f"(d[2]), "+f"(d[3])
        : "r"(a0), "r"(a1), "r"(a2), "r"(a3), "r"(b0), "r"(b1));
}
__device__ __forceinline__ uint32_t smem_u32(const void* p) {
    uint32_t a;
    asm("{ .reg .u64 t; cvta.to.shared.u64 t, %1; cvt.u32.u64 %0, t; }"
        : "=r"(a) : "l"(p));
    return a;
}
__device__ __forceinline__ void cpasync16(uint32_t dst, const void* src) {
    asm volatile("cp.async.ca.shared.global [%0], [%1], 16;"
                 :: "r"(dst), "l"(src));
}
#define CP_COMMIT() asm volatile("cp.async.commit_group;" ::: "memory")

// ===========================================================================
// K1 (merged, 256 threads): blocks 0-2 spectral norm; blocks 3-74 raw
// projections (256 n-columns each). 4+ warps/SMSP for latency hiding.
// ===========================================================================
#define SQ_ITERS 4
#define PW_ITERS 16

__global__ void __launch_bounds__(256) prep_kernel(
        const float* __restrict__ x,
        const float* __restrict__ Wq,
        const float* __restrict__ Wk,
        const float* __restrict__ Wv) {
    __shared__ float shb[8448];
    __shared__ float part[8];
    __shared__ float scal;
    int t = threadIdx.x;

    if (blockIdx.x < 3) {
        int mat = blockIdx.x;
        const float* W = (mat == 0) ? Wq : (mat == 1) ? Wk : Wv;
        int dim = (mat == 2) ? 64 : 8;
        float* Ga = shb;                 // 64*65
        float* Gb = shb + 4160;          // 64*65 (also W staging)
        float* vv = shb + 8320;          // 64

        for (int i = t; i < dim * 64; i += 256)
            Gb[(i >> 6) * 65 + (i & 63)] = W[i];
        __syncthreads();

        if (dim == 64) {
            int r = t >> 2, c0 = (t & 3) << 4;
            float rr[64];
#pragma unroll
            for (int j = 0; j < 64; j++) rr[j] = Gb[r * 65 + j];
            float acc[16];
#pragma unroll
            for (int cc = 0; cc < 16; cc++) acc[cc] = 0.f;
            for (int j = 0; j < 64; j++)
#pragma unroll
                for (int cc = 0; cc < 16; cc++)
                    acc[cc] += rr[j] * Gb[(c0 + cc) * 65 + j];
#pragma unroll
            for (int cc = 0; cc < 16; cc++) Ga[r * 65 + c0 + cc] = acc[cc];
        } else if (t < 64) {
            int r = t >> 3, c = t & 7;
            float s = 0.f;
            for (int j = 0; j < 64; j++) s += Gb[r * 65 + j] * Gb[c * 65 + j];
            Ga[r * 65 + c] = s;
        }
        __syncthreads();

        float logl = 0.f, pw = 1.f;
        float* src = Ga;
        float* dst = Gb;
        for (int it = 0; it < SQ_ITERS; it++) {
            float ss = 0.f;
            for (int e = t; e < dim * dim; e += 256) {
                float v = src[(e / dim) * 65 + (e % dim)];
                ss += v * v;
            }
#pragma unroll
            for (int o = 16; o > 0; o >>= 1)
                ss += __shfl_xor_sync(0xffffffffu, ss, o);
            if ((t & 31) == 0) part[t >> 5] = ss;
            __syncthreads();
            float tot = 0.f;
#pragma unroll
            for (int i = 0; i < 8; i++) tot += part[i];
            float fro = sqrtf(tot);
            float inv2 = 1.f / tot;
            logl += log2f(fro) * pw;
            pw *= 0.5f;

            if (dim == 64) {
                int r = t >> 2, c0 = (t & 3) << 4;
                float rr[64];
#pragma unroll
                for (int j = 0; j < 64; j++) rr[j] = src[r * 65 + j];
                float acc[16];
#pragma unroll
                for (int cc = 0; cc < 16; cc++) acc[cc] = 0.f;
                for (int j = 0; j < 64; j++)
#pragma unroll
                    for (int cc = 0; cc < 16; cc++)
                        acc[cc] += rr[j] * src[j * 65 + c0 + cc];
#pragma unroll
                for (int cc = 0; cc < 16; cc++)
                    dst[r * 65 + c0 + cc] = acc[cc] * inv2;
            } else if (t < 64) {
                int r = t >> 3, c = t & 7;
                float s = 0.f;
#pragma unroll
                for (int j = 0; j < 8; j++) s += src[r * 65 + j] * src[j * 65 + c];
                dst[r * 65 + c] = s * inv2;
            }
            __syncthreads();
            float* tmp = src; src = dst; dst = tmp;
        }

        if (t < 64) vv[t] = 1.f;
        __syncthreads();
        float lam = 1.f;
        for (int it = 0; it < PW_ITERS; it++) {
            float w = 0.f;
            if (t < dim) {
                const float* gr = src + t * 65;
                for (int j = 0; j < dim; j++) w += gr[j] * vv[j];
            }
            float sq = w * w;
#pragma unroll
            for (int o = 16; o > 0; o >>= 1)
                sq += __shfl_xor_sync(0xffffffffu, sq, o);
            if ((t & 31) == 0) part[t >> 5] = sq;
            __syncthreads();
            if (t == 0) scal = sqrtf(part[0] + part[1]);
            __syncthreads();
            lam = scal;
            if (t < dim) vv[t] = w / lam;
            __syncthreads();
        }
        if (t == 0) {
            float l0 = log2f(lam) * pw + logl;
            d_invsig[mat] = exp2f(-0.5f * l0);
        }
    } else {
        float* wq = shb;            // 512
        float* wk = shb + 512;      // 512
        float* wv = shb + 1024;     // 4096

        for (int i = t; i < 512; i += 256) { wq[i] = Wq[i]; wk[i] = Wk[i]; }
        for (int i = t; i < 4096; i += 256) wv[i] = Wv[i];
        __syncthreads();

        int gid = (blockIdx.x - 3) * 256 + t;       // 0 .. 18431
        int b = gid / NN, n = gid % NN;

        float fa[8] = {0.f}, ga[8] = {0.f}, ha[64] = {0.f};
        const float* xp = x + (size_t)b * CC * NN + n;
        for (int c = 0; c < 64; c++) {
            float xc = xp[(size_t)c * NN];
#pragma unroll
            for (int o = 0; o < 8; o++) {
                fa[o] += wq[o * 64 + c] * xc;
                ga[o] += wk[o * 64 + c] * xc;
            }
#pragma unroll
            for (int o = 0; o < 64; o++) ha[o] += wv[o * 64 + c] * xc;
        }

        // f: fp16 hi/lo pairs in m16n8k16 A-fragment layout.
        {
            int tl = n >> 4, r = n & 15;
            uint32_t* fb = d_f16 + ((size_t)(b * NTL + tl) * 32
                                    + 4 * (r & 7)) * 4 + ((r >> 3) & 1);
#pragma unroll
            for (int c = 0; c < 4; c++) {
                __half h0 = __float2half_rn(fa[2 * c]);
                __half h1 = __float2half_rn(fa[2 * c + 1]);
                float l0 = fa[2 * c]     - __half2float(h0);
                float l1 = fa[2 * c + 1] - __half2float(h1);
                uint32_t hi = ((uint32_t)__half_as_ushort(h1) << 16)
                            | __half_as_ushort(h0);
                fb[c * 4]     = hi;
                fb[c * 4 + 2] = pack_f16(l1, l0);
            }
        }
        // g
        size_t b8 = ((size_t)b * NN + n) * 8;
#pragma unroll
        for (int o = 0; o < 8; o++) d_g[b8 + o] = ga[o];
        // h: raw fp16 pairs [n][c]
        {
            uint32_t hw[32];
#pragma unroll
            for (int i = 0; i < 32; i++)
                hw[i] = pack_f16(ha[2 * i + 1], ha[2 * i]);
            uint4* hp = (uint4*)(d_h16 + ((size_t)b * NN + n) * 32);
#pragma unroll
            for (int j = 0; j < 8; j++)
                hp[j] = make_uint4(hw[4 * j], hw[4 * j + 1],
                                   hw[4 * j + 2], hw[4 * j + 3]);
        }

        // block max of ||f~||^2
        float n2 = 0.f;
#pragma unroll
        for (int o = 0; o < 8; o++) n2 += fa[o] * fa[o];
#pragma unroll
        for (int o = 16; o > 0; o >>= 1)
            n2 = fmaxf(n2, __shfl_xor_sync(0xffffffffu, n2, o));
        if ((t & 31) == 0) part[t >> 5] = n2;
        __syncthreads();
        if (t == 0) {
            float m = part[0];
#pragma unroll
            for (int i = 1; i < 8; i++) m = fmaxf(m, part[i]);
            d_fmax2[blockIdx.x - 3] = m;
        }
    }
}

// ===========================================================================
// K2: single-pass flash attention, fully tensor-core, KT=64.
//   Scores: fp16 mma on pre-split f fragments, register-prefetched 1 tile
//   ahead (L2 latency hidden). P via ex2.approx + movmatrix (regs only).
//   PV: raw fp16 h~ via cp.async ring (3 x 8KB) + ldmatrix.trans.
// 8 warps: warp w owns q-cols [8w, 8w+8), all 64 c rows.
// ===========================================================================
__global__ void __launch_bounds__(256, 2) attn_kernel(
        const float* __restrict__ x,
        const float* __restrict__ bq,
        const float* __restrict__ bk,
        const float* __restrict__ bv,
        const float* __restrict__ gamma,
        float* __restrict__ out) {
    __shared__ __align__(16) uint32_t hbuf[3][2048];   // 3 x 8KB fp16 H tiles
    __shared__ float g_sh[64 * 9];
    __shared__ float red8[8];

    int t    = threadIdx.x;
    int wid  = t >> 5;
    int lane = t & 31;
    int b    = blockIdx.y;
    int qt   = blockIdx.x;

    float iq = d_invsig[0], ik = d_invsig[1], iv = d_invsig[2];

    // stage g tile (scaled + bias)
    const float* gp = d_g + ((size_t)b * NN + qt * 64) * 8;
    for (int i = t; i < 512; i += 256)
        g_sh[(i >> 3) * 9 + (i & 7)] = ik * gp[i] + __ldg(bk + (i & 7));

    // Fmax^2 reduction (72 values)
    {
        float fm = (t < 72) ? d_fmax2[t] : 0.f;
#pragma unroll
        for (int o = 16; o > 0; o >>= 1)
            fm = fmaxf(fm, __shfl_xor_sync(0xffffffffu, fm, o));
        if (lane == 0) red8[wid] = fm;
    }

    // H staging role + prologue cp.async for tiles 0,1 (8KB each, 2 rows/thr)
    int srow = t >> 3, sj = t & 7;           // srow 0..31; rows srow, srow+32
    const char* hsrc = (const char*)d_h16
                     + ((size_t)(b * NN + srow)) * 128 + sj * 16;
    uint32_t hb0  = smem_u32(&hbuf[0][0]);
    uint32_t sdst = hb0 + srow * 128 + ((sj ^ (srow & 7)) << 4);
    cpasync16(sdst, hsrc);
    cpasync16(sdst + 4096, hsrc + 4096);
    CP_COMMIT();
    cpasync16(sdst + 8192, hsrc + 8192);
    cpasync16(sdst + 8192 + 4096, hsrc + 8192 + 4096);
    CP_COMMIT();

    __syncthreads();
    float Fmax;
    {
        float fm = red8[0];
#pragma unroll
        for (int i = 1; i < 8; i++) fm = fmaxf(fm, red8[i]);
        Fmax = sqrtf(fm);
    }

    // G B-fragments (fp16 hi/lo)
    uint32_t bgh, bgl;
    {
        int qn = 8 * wid + (lane >> 2);
        int d0 = 2 * (lane & 3);
        float g0 = g_sh[qn * 9 + d0];
        float g1 = g_sh[qn * 9 + d0 + 1];
        __half h0 = __float2half_rn(g0);
        __half h1 = __float2half_rn(g1);
        bgh = ((uint32_t)__half_as_ushort(h1) << 16) | __half_as_ushort(h0);
        bgl = pack_f16(g1 - __half2float(h1), g0 - __half2float(h0));
    }

    // exp2 constants for this lane's two q columns (qa, qa+1)
    int qa = 8 * wid + 2 * (lane & 3);
    float iq2 = iq * LOG2E;
    float cq20, cq21;
    {
        float n20 = 0.f, n21 = 0.f;
#pragma unroll
        for (int d = 0; d < 8; d++) {
            float v0 = g_sh[qa * 9 + d];
            float v1 = g_sh[(qa + 1) * 9 + d];
            n20 += v0 * v0;
            n21 += v1 * v1;
        }
        cq20 = (SHIFT - iq * Fmax * sqrtf(n20)) * LOG2E;
        cq21 = (SHIFT - iq * Fmax * sqrtf(n21)) * LOG2E;
    }

    // ldsm.trans A-frag address pieces
    int lm = lane & 7, g1b = (lane >> 3) & 1, g2b = lane >> 4;
    uint32_t rowbase = hb0 + (g2b * 8 + lm) * 128;
    uint32_t colX[4];
#pragma unroll
    for (int ct = 0; ct < 4; ct++)
        colX[ct] = (uint32_t)(((2 * ct + g1b) ^ lm) << 4);

    float acc[4][4];
#pragma unroll
    for (int i = 0; i < 4; i++)
#pragma unroll
        for (int j = 0; j < 4; j++) acc[i][j] = 0.f;
    float lsum0 = 0.f, lsum1 = 0.f;

    const uint4* fbase = (const uint4*)d_f16 + (size_t)b * NTL * 32 + lane;

    // prefetch f fragments for tile 0
    uint4 fA[4];
#pragma unroll
    for (int mt = 0; mt < 4; mt++)
        fA[mt] = __ldg(fbase + (size_t)mt * 32);

    for (int kt = 0; kt < NT; kt++) {
        int cur = kt % 3;

        // prefetch f for next tile (overlaps with everything below)
        uint4 fN[4];
        if (kt + 1 < NT) {
#pragma unroll
            for (int mt = 0; mt < 4; mt++)
                fN[mt] = __ldg(fbase + (size_t)((kt + 1) * 4 + mt) * 32);
        }

        if (kt < NT - 1)
            asm volatile("cp.async.wait_group 1;" ::: "memory");
        else
            asm volatile("cp.async.wait_group 0;" ::: "memory");
        __syncthreads();

        if (kt + 2 < NT) {
            uint32_t nb = ((kt + 2) % 3) * 8192;
            const char* hs = hsrc + (size_t)(kt + 2) * 8192;
            cpasync16(sdst + nb, hs);
            cpasync16(sdst + nb + 4096, hs + 4096);
            CP_COMMIT();
        }

        // ---- scores: fp16 mma on prefetched fragments ----
        uint32_t Bh[4][2];
#pragma unroll
        for (int mt = 0; mt < 4; mt++) {
            float D[4] = {0.f, 0.f, 0.f, 0.f};
            mma16h(D, fA[mt].x, fA[mt].y, fA[mt].z, fA[mt].w, bgh, bgh);
            mma16h(D, fA[mt].x, fA[mt].y, fA[mt].z, fA[mt].w, bgl, bgl);

            float p0 = ex2(fmaf(iq2, D[0], cq20));
            float p1 = ex2(fmaf(iq2, D[1], cq21));
            float p2 = ex2(fmaf(iq2, D[2], cq20));
            float p3 = ex2(fmaf(iq2, D[3], cq21));
            lsum0 += p0 + p2;
            lsum1 += p1 + p3;

            Bh[mt][0] = movm(pack_f16(p1, p0));   // keys mt*16+0..7
            Bh[mt][1] = movm(pack_f16(p3, p2));   // keys mt*16+8..15
        }

        // ---- PV: O += H~ * P ----
        uint32_t bufo = cur * 8192;
#pragma unroll
        for (int ct = 0; ct < 4; ct++) {
#pragma unroll
            for (int ks = 0; ks < 4; ks++) {
                uint32_t a0, a1, a2, a3;
                ldsm4t(a0, a1, a2, a3,
                       rowbase + bufo + ks * 2048 + colX[ct]);
                mma16h(acc[ct], a0, a1, a2, a3, Bh[ks][0], Bh[ks][1]);
            }
        }

#pragma unroll
        for (int mt = 0; mt < 4; mt++) fA[mt] = fN[mt];
    }

    // ---- denominator: sum over the 8 lane-rows sharing (l&3) ----
    lsum0 += __shfl_xor_sync(0xffffffffu, lsum0, 4);
    lsum0 += __shfl_xor_sync(0xffffffffu, lsum0, 8);
    lsum0 += __shfl_xor_sync(0xffffffffu, lsum0, 16);
    lsum1 += __shfl_xor_sync(0xffffffffu, lsum1, 4);
    lsum1 += __shfl_xor_sync(0xffffffffu, lsum1, 8);
    lsum1 += __shfl_xor_sync(0xffffffffu, lsum1, 16);
    float li0 = 1.f / lsum0;
    float li1 = 1.f / lsum1;

    // ---- epilogue: out = gam*iv*O~/l + gam*bv + x ----
    float gam = gamma[0];
    float giv = gam * iv;
#pragma unroll
    for (int ct = 0; ct < 4; ct++) {
        int c0 = ct * 16 + (lane >> 2);
        float gb0 = gam * __ldg(bv + c0);
        float gb1 = gam * __ldg(bv + c0 + 8);

        size_t base0 = ((size_t)b * CC + c0) * NN + (size_t)qt * 64 + qa;
        float2 x0 = *(const float2*)(x + base0);
        float2 r0;
        r0.x = giv * acc[ct][0] * li0 + gb0 + x0.x;
        r0.y = giv * acc[ct][1] * li1 + gb0 + x0.y;
        *(float2*)(out + base0) = r0;

        size_t base1 = base0 + (size_t)8 * NN;
        float2 x1 = *(const float2*)(x + base1);
        float2 r1;
        r1.x = giv * acc[ct][2] * li0 + gb1 + x1.x;
        r1.y = giv * acc[ct][3] * li1 + gb1 + x1.y;
        *(float2*)(out + base1) = r1;
    }
}

// ===========================================================================
extern "C" void kernel_launch(void* const* d_in, const int* in_sizes, int n_in,
                              void* d_out, int out_size) {
    const float* x     = (const float*)d_in[0];
    const float* Wq    = (const float*)d_in[1];
    const float* bq    = (const float*)d_in[2];
    const float* Wk    = (const float*)d_in[3];
    const float* bk    = (const float*)d_in[4];
    const float* Wv    = (const float*)d_in[5];
    const float* bv    = (const float*)d_in[6];
    const float* gamma = (const float*)d_in[7];
    float* out = (float*)d_out;
    (void)bq;

    prep_kernel<<<3 + (BB * NN) / 256, 256>>>(x, Wq, Wk, Wv);
    attn_kernel<<<dim3(NN / 64, BB), 256>>>(x, bq, bk, bv, gamma, out);
}

// round 15
// speedup vs baseline: 3.9730x; 1.0542x over previous
#include <cuda_runtime.h>
#include <cuda_fp16.h>
#include <math.h>
#include <stdint.h>

// Problem constants
#define NN 9216      // H*W = 96*96
#define CC 64        // channels
#define C8 8         // C/8
#define BB 2         // batch
#define KT 64        // key tile
#define NT (NN / KT) // 144 tiles
#define QT 128       // query tile per CTA
#define NTL 576      // NN/16 f-tiles per batch
#define SHIFT 9.70406053f   // 14*ln2: P scaled by 2^14 (cancels in O/l)
#define LOG2E 1.44269504f

// -------- scratch (static device globals: no runtime allocation) ----------
__device__ float    d_invsig[3];                // 1/sigma for Wq, Wk, Wv
__device__ uint32_t d_f16[BB * NTL * 32 * 4];   // f~ hi/lo fp16 A-fragments
__device__ float    d_g[BB * NN * C8];          // raw queries g~ = Wk x
__device__ uint32_t d_h16[BB * NN * 32];        // raw h~ fp16 pairs [n][c]
__device__ float    d_fmax2[72];                // per-prep-block max ||f~||^2

// ---------------- helpers -----------------
__device__ __forceinline__ uint32_t pack_f16(float hi, float lo) {
    uint32_t r;
    asm("cvt.rn.f16x2.f32 %0, %1, %2;" : "=r"(r) : "f"(hi), "f"(lo));
    return r;
}
__device__ __forceinline__ float ex2(float x) {
    float y;
    asm("ex2.approx.f32 %0, %1;" : "=f"(y) : "f"(x));
    return y;
}
__device__ __forceinline__ uint32_t movm(uint32_t s) {
    uint32_t d;
    asm("movmatrix.sync.aligned.m8n8.trans.b16 %0, %1;" : "=r"(d) : "r"(s));
    return d;
}
__device__ __forceinline__ void ldsm4t(uint32_t& a0, uint32_t& a1,
                                       uint32_t& a2, uint32_t& a3, uint32_t addr) {
    asm volatile("ldmatrix.sync.aligned.m8n8.x4.trans.shared.b16 {%0,%1,%2,%3}, [%4];"
                 : "=r"(a0), "=r"(a1), "=r"(a2), "=r"(a3) : "r"(addr));
}
__device__ __forceinline__ void mma16h(float* d,
        uint32_t a0, uint32_t a1, uint32_t a2, uint32_t a3,
        uint32_t b0, uint32_t b1) {
    asm volatile(
        "mma.sync.aligned.m16n8k16.row.col.f32.f16.f16.f32 "
        "{%0,%1,%2,%3},{%4,%5,%6,%7},{%8,%9},{%0,%1,%2,%3};"
        : "+f"(d[0]), "+f"(d[1]), "+f"(d[2]), "+f"(d[3])
        : "r"(a0), "r"(a1), "r"(a2), "r"(a3), "r"(b0), "r"(b1));
}
__device__ __forceinline__ uint32_t smem_u32(const void* p) {
    uint32_t a;
    asm("{ .reg .u64 t; cvta.to.shared.u64 t, %1; cvt.u32.u64 %0, t; }"
        : "=r"(a) : "l"(p));
    return a;
}
__device__ __forceinline__ void cpasync16(uint32_t dst, const void* src) {
    asm volatile("cp.async.ca.shared.global [%0], [%1], 16;"
                 :: "r"(dst), "l"(src));
}
#define CP_COMMIT() asm volatile("cp.async.commit_group;" ::: "memory")

// ===========================================================================
// K1 (merged, 256 threads): blocks 0-2 spectral norm; blocks 3-74 raw
// projections (256 n-columns each).
// ===========================================================================
#define SQ_ITERS 4
#define PW_ITERS 16

__global__ void __launch_bounds__(256) prep_kernel(
        const float* __restrict__ x,
        const float* __restrict__ Wq,
        const float* __restrict__ Wk,
        const float* __restrict__ Wv) {
    __shared__ float shb[8448];
    __shared__ float part[8];
    __shared__ float scal;
    int t = threadIdx.x;

    if (blockIdx.x < 3) {
        int mat = blockIdx.x;
        const float* W = (mat == 0) ? Wq : (mat == 1) ? Wk : Wv;
        int dim = (mat == 2) ? 64 : 8;
        float* Ga = shb;                 // 64*65
        float* Gb = shb + 4160;          // 64*65 (also W staging)
        float* vv = shb + 8320;          // 64

        for (int i = t; i < dim * 64; i += 256)
            Gb[(i >> 6) * 65 + (i & 63)] = W[i];
        __syncthreads();

        if (dim == 64) {
            int r = t >> 2, c0 = (t & 3) << 4;
            float rr[64];
#pragma unroll
            for (int j = 0; j < 64; j++) rr[j] = Gb[r * 65 + j];
            float acc[16];
#pragma unroll
            for (int cc = 0; cc < 16; cc++) acc[cc] = 0.f;
            for (int j = 0; j < 64; j++)
#pragma unroll
                for (int cc = 0; cc < 16; cc++)
                    acc[cc] += rr[j] * Gb[(c0 + cc) * 65 + j];
#pragma unroll
            for (int cc = 0; cc < 16; cc++) Ga[r * 65 + c0 + cc] = acc[cc];
        } else if (t < 64) {
            int r = t >> 3, c = t & 7;
            float s = 0.f;
            for (int j = 0; j < 64; j++) s += Gb[r * 65 + j] * Gb[c * 65 + j];
            Ga[r * 65 + c] = s;
        }
        __syncthreads();

        float logl = 0.f, pw = 1.f;
        float* src = Ga;
        float* dst = Gb;
        for (int it = 0; it < SQ_ITERS; it++) {
            float ss = 0.f;
            for (int e = t; e < dim * dim; e += 256) {
                float v = src[(e / dim) * 65 + (e % dim)];
                ss += v * v;
            }
#pragma unroll
            for (int o = 16; o > 0; o >>= 1)
                ss += __shfl_xor_sync(0xffffffffu, ss, o);
            if ((t & 31) == 0) part[t >> 5] = ss;
            __syncthreads();
            float tot = 0.f;
#pragma unroll
            for (int i = 0; i < 8; i++) tot += part[i];
            float fro = sqrtf(tot);
            float inv2 = 1.f / tot;
            logl += log2f(fro) * pw;
            pw *= 0.5f;

            if (dim == 64) {
                int r = t >> 2, c0 = (t & 3) << 4;
                float rr[64];
#pragma unroll
                for (int j = 0; j < 64; j++) rr[j] = src[r * 65 + j];
                float acc[16];
#pragma unroll
                for (int cc = 0; cc < 16; cc++) acc[cc] = 0.f;
                for (int j = 0; j < 64; j++)
#pragma unroll
                    for (int cc = 0; cc < 16; cc++)
                        acc[cc] += rr[j] * src[j * 65 + c0 + cc];
#pragma unroll
                for (int cc = 0; cc < 16; cc++)
                    dst[r * 65 + c0 + cc] = acc[cc] * inv2;
            } else if (t < 64) {
                int r = t >> 3, c = t & 7;
                float s = 0.f;
#pragma unroll
                for (int j = 0; j < 8; j++) s += src[r * 65 + j] * src[j * 65 + c];
                dst[r * 65 + c] = s * inv2;
            }
            __syncthreads();
            float* tmp = src; src = dst; dst = tmp;
        }

        if (t < 64) vv[t] = 1.f;
        __syncthreads();
        float lam = 1.f;
        for (int it = 0; it < PW_ITERS; it++) {
            float w = 0.f;
            if (t < dim) {
                const float* gr = src + t * 65;
                for (int j = 0; j < dim; j++) w += gr[j] * vv[j];
            }
            float sq = w * w;
#pragma unroll
            for (int o = 16; o > 0; o >>= 1)
                sq += __shfl_xor_sync(0xffffffffu, sq, o);
            if ((t & 31) == 0) part[t >> 5] = sq;
            __syncthreads();
            if (t == 0) scal = sqrtf(part[0] + part[1]);
            __syncthreads();
            lam = scal;
            if (t < dim) vv[t] = w / lam;
            __syncthreads();
        }
        if (t == 0) {
            float l0 = log2f(lam) * pw + logl;
            d_invsig[mat] = exp2f(-0.5f * l0);
        }
    } else {
        float* wq = shb;            // 512
        float* wk = shb + 512;      // 512
        float* wv = shb + 1024;     // 4096

        for (int i = t; i < 512; i += 256) { wq[i] = Wq[i]; wk[i] = Wk[i]; }
        for (int i = t; i < 4096; i += 256) wv[i] = Wv[i];
        __syncthreads();

        int gid = (blockIdx.x - 3) * 256 + t;       // 0 .. 18431
        int b = gid / NN, n = gid % NN;

        float fa[8] = {0.f}, ga[8] = {0.f}, ha[64] = {0.f};
        const float* xp = x + (size_t)b * CC * NN + n;
        for (int c = 0; c < 64; c++) {
            float xc = xp[(size_t)c * NN];
#pragma unroll
            for (int o = 0; o < 8; o++) {
                fa[o] += wq[o * 64 + c] * xc;
                ga[o] += wk[o * 64 + c] * xc;
            }
#pragma unroll
            for (int o = 0; o < 64; o++) ha[o] += wv[o * 64 + c] * xc;
        }

        // f: fp16 hi/lo pairs in m16n8k16 A-fragment layout.
        {
            int tl = n >> 4, r = n & 15;
            uint32_t* fb = d_f16 + ((size_t)(b * NTL + tl) * 32
                                    + 4 * (r & 7)) * 4 + ((r >> 3) & 1);
#pragma unroll
            for (int c = 0; c < 4; c++) {
                __half h0 = __float2half_rn(fa[2 * c]);
                __half h1 = __float2half_rn(fa[2 * c + 1]);
                float l0 = fa[2 * c]     - __half2float(h0);
                float l1 = fa[2 * c + 1] - __half2float(h1);
                uint32_t hi = ((uint32_t)__half_as_ushort(h1) << 16)
                            | __half_as_ushort(h0);
                fb[c * 4]     = hi;
                fb[c * 4 + 2] = pack_f16(l1, l0);
            }
        }
        // g
        size_t b8 = ((size_t)b * NN + n) * 8;
#pragma unroll
        for (int o = 0; o < 8; o++) d_g[b8 + o] = ga[o];
        // h: raw fp16 pairs [n][c]
        {
            uint32_t hw[32];
#pragma unroll
            for (int i = 0; i < 32; i++)
                hw[i] = pack_f16(ha[2 * i + 1], ha[2 * i]);
            uint4* hp = (uint4*)(d_h16 + ((size_t)b * NN + n) * 32);
#pragma unroll
            for (int j = 0; j < 8; j++)
                hp[j] = make_uint4(hw[4 * j], hw[4 * j + 1],
                                   hw[4 * j + 2], hw[4 * j + 3]);
        }

        // block max of ||f~||^2
        float n2 = 0.f;
#pragma unroll
        for (int o = 0; o < 8; o++) n2 += fa[o] * fa[o];
#pragma unroll
        for (int o = 16; o > 0; o >>= 1)
            n2 = fmaxf(n2, __shfl_xor_sync(0xffffffffu, n2, o));
        if ((t & 31) == 0) part[t >> 5] = n2;
        __syncthreads();
        if (t == 0) {
            float m = part[0];
#pragma unroll
            for (int i = 1; i < 8; i++) m = fmaxf(m, part[i]);
            d_fmax2[blockIdx.x - 3] = m;
        }
    }
}

// ===========================================================================
// K2: single-pass flash attention, fully tensor-core, KT=64, QT=128.
//   Each warp owns 16 queries (two n=8 B-frag groups): every ldsm A-frag
//   feeds 2 PV mma -> H-side L1 traffic per query halves vs QT=64.
//   Grid = 72 x 2 = 144 CTAs = one full wave.
// ===========================================================================
__global__ void __launch_bounds__(256, 1) attn_kernel(
        const float* __restrict__ x,
        const float* __restrict__ bq,
        const float* __restrict__ bk,
        const float* __restrict__ bv,
        const float* __restrict__ gamma,
        float* __restrict__ out) {
    __shared__ __align__(16) uint32_t hbuf[3][2048];   // 3 x 8KB fp16 H tiles
    __shared__ float g_sh[QT * 9];
    __shared__ float red8[8];

    int t    = threadIdx.x;
    int wid  = t >> 5;
    int lane = t & 31;
    int b    = blockIdx.y;
    int qt   = blockIdx.x;

    float iq = d_invsig[0], ik = d_invsig[1], iv = d_invsig[2];

    // stage g tile (scaled + bias): 128 queries
    const float* gp = d_g + ((size_t)b * NN + (size_t)qt * QT) * 8;
    for (int i = t; i < QT * 8; i += 256)
        g_sh[(i >> 3) * 9 + (i & 7)] = ik * gp[i] + __ldg(bk + (i & 7));

    // Fmax^2 reduction (72 values)
    {
        float fm = (t < 72) ? d_fmax2[t] : 0.f;
#pragma unroll
        for (int o = 16; o > 0; o >>= 1)
            fm = fmaxf(fm, __shfl_xor_sync(0xffffffffu, fm, o));
        if (lane == 0) red8[wid] = fm;
    }

    // H staging role + prologue cp.async for tiles 0,1 (8KB each)
    int srow = t >> 3, sj = t & 7;           // rows srow, srow+32
    const char* hsrc = (const char*)d_h16
                     + ((size_t)(b * NN + srow)) * 128 + sj * 16;
    uint32_t hb0  = smem_u32(&hbuf[0][0]);
    uint32_t sdst = hb0 + srow * 128 + ((sj ^ (srow & 7)) << 4);
    cpasync16(sdst, hsrc);
    cpasync16(sdst + 4096, hsrc + 4096);
    CP_COMMIT();
    cpasync16(sdst + 8192, hsrc + 8192);
    cpasync16(sdst + 8192 + 4096, hsrc + 8192 + 4096);
    CP_COMMIT();

    __syncthreads();
    float Fmax;
    {
        float fm = red8[0];
#pragma unroll
        for (int i = 1; i < 8; i++) fm = fmaxf(fm, red8[i]);
        Fmax = sqrtf(fm);
    }

    // G B-fragments (fp16 hi/lo) for 2 query groups: qg0 = 16w+(l>>2), qg1 = +8
    uint32_t bgh[2], bgl[2];
#pragma unroll
    for (int qg = 0; qg < 2; qg++) {
        int qn = 16 * wid + 8 * qg + (lane >> 2);
        int d0 = 2 * (lane & 3);
        float g0 = g_sh[qn * 9 + d0];
        float g1 = g_sh[qn * 9 + d0 + 1];
        __half h0 = __float2half_rn(g0);
        __half h1 = __float2half_rn(g1);
        bgh[qg] = ((uint32_t)__half_as_ushort(h1) << 16) | __half_as_ushort(h0);
        bgl[qg] = pack_f16(g1 - __half2float(h1), g0 - __half2float(h0));
    }

    // exp2 constants: lane's q columns qa, qa+1 per group
    float iq2 = iq * LOG2E;
    float cq2[2][2];
#pragma unroll
    for (int qg = 0; qg < 2; qg++) {
        int qa = 16 * wid + 8 * qg + 2 * (lane & 3);
#pragma unroll
        for (int u = 0; u < 2; u++) {
            float n2 = 0.f;
#pragma unroll
            for (int d = 0; d < 8; d++) {
                float v = g_sh[(qa + u) * 9 + d];
                n2 += v * v;
            }
            cq2[qg][u] = (SHIFT - iq * Fmax * sqrtf(n2)) * LOG2E;
        }
    }

    // ldsm.trans A-frag address pieces
    int lm = lane & 7, g1b = (lane >> 3) & 1, g2b = lane >> 4;
    uint32_t rowbase = hb0 + (g2b * 8 + lm) * 128;
    uint32_t colX[4];
#pragma unroll
    for (int ct = 0; ct < 4; ct++)
        colX[ct] = (uint32_t)(((2 * ct + g1b) ^ lm) << 4);

    float acc[4][2][4];
#pragma unroll
    for (int i = 0; i < 4; i++)
#pragma unroll
        for (int qg = 0; qg < 2; qg++)
#pragma unroll
            for (int j = 0; j < 4; j++) acc[i][qg][j] = 0.f;
    float ls[2][2] = {{0.f, 0.f}, {0.f, 0.f}};

    const uint4* fbase = (const uint4*)d_f16 + (size_t)b * NTL * 32 + lane;

    // prefetch f fragments for tile 0
    uint4 fA[4];
#pragma unroll
    for (int mt = 0; mt < 4; mt++)
        fA[mt] = __ldg(fbase + (size_t)mt * 32);

    for (int kt = 0; kt < NT; kt++) {
        int cur = kt % 3;

        // prefetch f for next tile
        uint4 fN[4];
        if (kt + 1 < NT) {
#pragma unroll
            for (int mt = 0; mt < 4; mt++)
                fN[mt] = __ldg(fbase + (size_t)((kt + 1) * 4 + mt) * 32);
        }

        if (kt < NT - 1)
            asm volatile("cp.async.wait_group 1;" ::: "memory");
        else
            asm volatile("cp.async.wait_group 0;" ::: "memory");
        __syncthreads();

        if (kt + 2 < NT) {
            uint32_t nb = ((kt + 2) % 3) * 8192;
            const char* hs = hsrc + (size_t)(kt + 2) * 8192;
            cpasync16(sdst + nb, hs);
            cpasync16(sdst + nb + 4096, hs + 4096);
            CP_COMMIT();
        }

        // ---- scores: fp16 mma on prefetched fragments, 2 q-groups ----
        uint32_t Bh[4][2][2];
#pragma unroll
        for (int mt = 0; mt < 4; mt++) {
#pragma unroll
            for (int qg = 0; qg < 2; qg++) {
                float D[4] = {0.f, 0.f, 0.f, 0.f};
                mma16h(D, fA[mt].x, fA[mt].y, fA[mt].z, fA[mt].w,
                       bgh[qg], bgh[qg]);
                mma16h(D, fA[mt].x, fA[mt].y, fA[mt].z, fA[mt].w,
                       bgl[qg], bgl[qg]);

                float p0 = ex2(fmaf(iq2, D[0], cq2[qg][0]));
                float p1 = ex2(fmaf(iq2, D[1], cq2[qg][1]));
                float p2 = ex2(fmaf(iq2, D[2], cq2[qg][0]));
                float p3 = ex2(fmaf(iq2, D[3], cq2[qg][1]));
                ls[qg][0] += p0 + p2;
                ls[qg][1] += p1 + p3;

                Bh[mt][qg][0] = movm(pack_f16(p1, p0));
                Bh[mt][qg][1] = movm(pack_f16(p3, p2));
            }
        }

        // ---- PV: O += H~ * P (each ldsm feeds 2 mma) ----
        uint32_t bufo = cur * 8192;
#pragma unroll
        for (int ct = 0; ct < 4; ct++) {
#pragma unroll
            for (int ks = 0; ks < 4; ks++) {
                uint32_t a0, a1, a2, a3;
                ldsm4t(a0, a1, a2, a3,
                       rowbase + bufo + ks * 2048 + colX[ct]);
                mma16h(acc[ct][0], a0, a1, a2, a3, Bh[ks][0][0], Bh[ks][0][1]);
                mma16h(acc[ct][1], a0, a1, a2, a3, Bh[ks][1][0], Bh[ks][1][1]);
            }
        }

#pragma unroll
        for (int mt = 0; mt < 4; mt++) fA[mt] = fN[mt];
    }

    // ---- denominators ----
#pragma unroll
    for (int qg = 0; qg < 2; qg++) {
#pragma unroll
        for (int u = 0; u < 2; u++) {
            float v = ls[qg][u];
            v += __shfl_xor_sync(0xffffffffu, v, 4);
            v += __shfl_xor_sync(0xffffffffu, v, 8);
            v += __shfl_xor_sync(0xffffffffu, v, 16);
            ls[qg][u] = 1.f / v;
        }
    }

    // ---- epilogue: out = gam*iv*O~/l + gam*bv + x ----
    float gam = gamma[0];
    float giv = gam * iv;
#pragma unroll
    for (int ct = 0; ct < 4; ct++) {
        int c0 = ct * 16 + (lane >> 2);
        float gb0 = gam * __ldg(bv + c0);
        float gb1 = gam * __ldg(bv + c0 + 8);
#pragma unroll
        for (int qg = 0; qg < 2; qg++) {
            int q0 = 16 * wid + 8 * qg + 2 * (lane & 3);
            float li0 = ls[qg][0], li1 = ls[qg][1];

            size_t base0 = ((size_t)b * CC + c0) * NN
                         + (size_t)qt * QT + q0;
            float2 x0 = *(const float2*)(x + base0);
            float2 r0;
            r0.x = giv * acc[ct][qg][0] * li0 + gb0 + x0.x;
            r0.y = giv * acc[ct][qg][1] * li1 + gb0 + x0.y;
            *(float2*)(out + base0) = r0;

            size_t base1 = base0 + (size_t)8 * NN;
            float2 x1 = *(const float2*)(x + base1);
            float2 r1;
            r1.x = giv * acc[ct][qg][2] * li0 + gb1 + x1.x;
            r1.y = giv * acc[ct][qg][3] * li1 + gb1 + x1.y;
            *(float2*)(out + base1) = r1;
        }
    }
}

// ===========================================================================
extern "C" void kernel_launch(void* const* d_in, const int* in_sizes, int n_in,
                              void* d_out, int out_size) {
    const float* x     = (const float*)d_in[0];
    const float* Wq    = (const float*)d_in[1];
    const float* bq    = (const float*)d_in[2];
    const float* Wk    = (const float*)d_in[3];
    const float* bk    = (const float*)d_in[4];
    const float* Wv    = (const float*)d_in[5];
    const float* bv    = (const float*)d_in[6];
    const float* gamma = (const float*)d_in[7];
    float* out = (float*)d_out;
    (void)bq;

    prep_kernel<<<3 + (BB * NN) / 256, 256>>>(x, Wq, Wk, Wv);
    attn_kernel<<<dim3(NN / QT, BB), 256>>>(x, bq, bk, bv, gamma, out);
}

// round 16
// speedup vs baseline: 4.4255x; 1.1139x over previous
#include <cuda_runtime.h>
#include <cuda_fp16.h>
#include <math.h>
#include <stdint.h>

// Problem constants
#define NN 9216      // H*W = 96*96
#define CC 64        // channels
#define C8 8         // C/8
#define BB 2         // batch
#define KT 64        // key tile
#define NT (NN / KT) // 144 tiles total
#define NTH (NT / 2) // 72 tiles per key-half
#define QT 128       // query tile per CTA
#define NQT (NN / QT)// 72 query tiles
#define NTL 576      // NN/16 f-tiles per batch
#define SHIFT 9.70406053f   // 14*ln2: P scaled by 2^14 (cancels in O/l)
#define LOG2E 1.44269504f

// -------- scratch (static device globals: no runtime allocation) ----------
__device__ float    d_invsig[3];                // 1/sigma for Wq, Wk, Wv
__device__ uint32_t d_f16[BB * NTL * 32 * 4];   // f~ hi/lo fp16 A-fragments
__device__ float    d_g[BB * NN * C8];          // raw queries g~ = Wk x
__device__ uint32_t d_h16[BB * NN * 32];        // raw h~ fp16 pairs [n][c]
__device__ float    d_fmax2[72];                // per-prep-block max ||f~||^2
__device__ float    d_pO[BB * NQT * 2 * CC * QT];  // partial O~ [b][qt][z][c][q]
__device__ float    d_pl[BB * NQT * 2 * QT];       // partial l

// ---------------- helpers -----------------
__device__ __forceinline__ uint32_t pack_f16(float hi, float lo) {
    uint32_t r;
    asm("cvt.rn.f16x2.f32 %0, %1, %2;" : "=r"(r) : "f"(hi), "f"(lo));
    return r;
}
__device__ __forceinline__ float ex2(float x) {
    float y;
    asm("ex2.approx.f32 %0, %1;" : "=f"(y) : "f"(x));
    return y;
}
__device__ __forceinline__ uint32_t movm(uint32_t s) {
    uint32_t d;
    asm("movmatrix.sync.aligned.m8n8.trans.b16 %0, %1;" : "=r"(d) : "r"(s));
    return d;
}
__device__ __forceinline__ void ldsm4t(uint32_t& a0, uint32_t& a1,
                                       uint32_t& a2, uint32_t& a3, uint32_t addr) {
    asm volatile("ldmatrix.sync.aligned.m8n8.x4.trans.shared.b16 {%0,%1,%2,%3}, [%4];"
                 : "=r"(a0), "=r"(a1), "=r"(a2), "=r"(a3) : "r"(addr));
}
__device__ __forceinline__ void mma16h(float* d,
        uint32_t a0, uint32_t a1, uint32_t a2, uint32_t a3,
        uint32_t b0, uint32_t b1) {
    asm volatile(
        "mma.sync.aligned.m16n8k16.row.col.f32.f16.f16.f32 "
        "{%0,%1,%2,%3},{%4,%5,%6,%7},{%8,%9},{%0,%1,%2,%3};"
        : "+f"(d[0]), "+f"(d[1]), "+f"(d[2]), "+f"(d[3])
        : "r"(a0), "r"(a1), "r"(a2), "r"(a3), "r"(b0), "r"(b1));
}
__device__ __forceinline__ uint32_t smem_u32(const void* p) {
    uint32_t a;
    asm("{ .reg .u64 t; cvta.to.shared.u64 t, %1; cvt.u32.u64 %0, t; }"
        : "=r"(a) : "l"(p));
    return a;
}
__device__ __forceinline__ void cpasync16(uint32_t dst, const void* src) {
    asm volatile("cp.async.ca.shared.global [%0], [%1], 16;"
                 :: "r"(dst), "l"(src));
}
#define CP_COMMIT() asm volatile("cp.async.commit_group;" ::: "memory")

// ===========================================================================
// K1 (merged, 256 threads): blocks 0-2 spectral norm; blocks 3-74 raw
// projections (256 n-columns each).
// ===========================================================================
#define SQ_ITERS 4
#define PW_ITERS 16

__global__ void __launch_bounds__(256) prep_kernel(
        const float* __restrict__ x,
        const float* __restrict__ Wq,
        const float* __restrict__ Wk,
        const float* __restrict__ Wv) {
    __shared__ float shb[8448];
    __shared__ float part[8];
    __shared__ float scal;
    int t = threadIdx.x;

    if (blockIdx.x < 3) {
        int mat = blockIdx.x;
        const float* W = (mat == 0) ? Wq : (mat == 1) ? Wk : Wv;
        int dim = (mat == 2) ? 64 : 8;
        float* Ga = shb;                 // 64*65
        float* Gb = shb + 4160;          // 64*65 (also W staging)
        float* vv = shb + 8320;          // 64

        for (int i = t; i < dim * 64; i += 256)
            Gb[(i >> 6) * 65 + (i & 63)] = W[i];
        __syncthreads();

        if (dim == 64) {
            int r = t >> 2, c0 = (t & 3) << 4;
            float rr[64];
#pragma unroll
            for (int j = 0; j < 64; j++) rr[j] = Gb[r * 65 + j];
            float acc[16];
#pragma unroll
            for (int cc = 0; cc < 16; cc++) acc[cc] = 0.f;
            for (int j = 0; j < 64; j++)
#pragma unroll
                for (int cc = 0; cc < 16; cc++)
                    acc[cc] += rr[j] * Gb[(c0 + cc) * 65 + j];
#pragma unroll
            for (int cc = 0; cc < 16; cc++) Ga[r * 65 + c0 + cc] = acc[cc];
        } else if (t < 64) {
            int r = t >> 3, c = t & 7;
            float s = 0.f;
            for (int j = 0; j < 64; j++) s += Gb[r * 65 + j] * Gb[c * 65 + j];
            Ga[r * 65 + c] = s;
        }
        __syncthreads();

        float logl = 0.f, pw = 1.f;
        float* src = Ga;
        float* dst = Gb;
        for (int it = 0; it < SQ_ITERS; it++) {
            float ss = 0.f;
            for (int e = t; e < dim * dim; e += 256) {
                float v = src[(e / dim) * 65 + (e % dim)];
                ss += v * v;
            }
#pragma unroll
            for (int o = 16; o > 0; o >>= 1)
                ss += __shfl_xor_sync(0xffffffffu, ss, o);
            if ((t & 31) == 0) part[t >> 5] = ss;
            __syncthreads();
            float tot = 0.f;
#pragma unroll
            for (int i = 0; i < 8; i++) tot += part[i];
            float fro = sqrtf(tot);
            float inv2 = 1.f / tot;
            logl += log2f(fro) * pw;
            pw *= 0.5f;

            if (dim == 64) {
                int r = t >> 2, c0 = (t & 3) << 4;
                float rr[64];
#pragma unroll
                for (int j = 0; j < 64; j++) rr[j] = src[r * 65 + j];
                float acc[16];
#pragma unroll
                for (int cc = 0; cc < 16; cc++) acc[cc] = 0.f;
                for (int j = 0; j < 64; j++)
#pragma unroll
                    for (int cc = 0; cc < 16; cc++)
                        acc[cc] += rr[j] * src[j * 65 + c0 + cc];
#pragma unroll
                for (int cc = 0; cc < 16; cc++)
                    dst[r * 65 + c0 + cc] = acc[cc] * inv2;
            } else if (t < 64) {
                int r = t >> 3, c = t & 7;
                float s = 0.f;
#pragma unroll
                for (int j = 0; j < 8; j++) s += src[r * 65 + j] * src[j * 65 + c];
                dst[r * 65 + c] = s * inv2;
            }
            __syncthreads();
            float* tmp = src; src = dst; dst = tmp;
        }

        if (t < 64) vv[t] = 1.f;
        __syncthreads();
        float lam = 1.f;
        for (int it = 0; it < PW_ITERS; it++) {
            float w = 0.f;
            if (t < dim) {
                const float* gr = src + t * 65;
                for (int j = 0; j < dim; j++) w += gr[j] * vv[j];
            }
            float sq = w * w;
#pragma unroll
            for (int o = 16; o > 0; o >>= 1)
                sq += __shfl_xor_sync(0xffffffffu, sq, o);
            if ((t & 31) == 0) part[t >> 5] = sq;
            __syncthreads();
            if (t == 0) scal = sqrtf(part[0] + part[1]);
            __syncthreads();
            lam = scal;
            if (t < dim) vv[t] = w / lam;
            __syncthreads();
        }
        if (t == 0) {
            float l0 = log2f(lam) * pw + logl;
            d_invsig[mat] = exp2f(-0.5f * l0);
        }
    } else {
        float* wq = shb;            // 512
        float* wk = shb + 512;      // 512
        float* wv = shb + 1024;     // 4096

        for (int i = t; i < 512; i += 256) { wq[i] = Wq[i]; wk[i] = Wk[i]; }
        for (int i = t; i < 4096; i += 256) wv[i] = Wv[i];
        __syncthreads();

        int gid = (blockIdx.x - 3) * 256 + t;       // 0 .. 18431
        int b = gid / NN, n = gid % NN;

        float fa[8] = {0.f}, ga[8] = {0.f}, ha[64] = {0.f};
        const float* xp = x + (size_t)b * CC * NN + n;
        for (int c = 0; c < 64; c++) {
            float xc = xp[(size_t)c * NN];
#pragma unroll
            for (int o = 0; o < 8; o++) {
                fa[o] += wq[o * 64 + c] * xc;
                ga[o] += wk[o * 64 + c] * xc;
            }
#pragma unroll
            for (int o = 0; o < 64; o++) ha[o] += wv[o * 64 + c] * xc;
        }

        // f: fp16 hi/lo pairs in m16n8k16 A-fragment layout.
        {
            int tl = n >> 4, r = n & 15;
            uint32_t* fb = d_f16 + ((size_t)(b * NTL + tl) * 32
                                    + 4 * (r & 7)) * 4 + ((r >> 3) & 1);
#pragma unroll
            for (int c = 0; c < 4; c++) {
                __half h0 = __float2half_rn(fa[2 * c]);
                __half h1 = __float2half_rn(fa[2 * c + 1]);
                float l0 = fa[2 * c]     - __half2float(h0);
                float l1 = fa[2 * c + 1] - __half2float(h1);
                uint32_t hi = ((uint32_t)__half_as_ushort(h1) << 16)
                            | __half_as_ushort(h0);
                fb[c * 4]     = hi;
                fb[c * 4 + 2] = pack_f16(l1, l0);
            }
        }
        // g
        size_t b8 = ((size_t)b * NN + n) * 8;
#pragma unroll
        for (int o = 0; o < 8; o++) d_g[b8 + o] = ga[o];
        // h: raw fp16 pairs [n][c]
        {
            uint32_t hw[32];
#pragma unroll
            for (int i = 0; i < 32; i++)
                hw[i] = pack_f16(ha[2 * i + 1], ha[2 * i]);
            uint4* hp = (uint4*)(d_h16 + ((size_t)b * NN + n) * 32);
#pragma unroll
            for (int j = 0; j < 8; j++)
                hp[j] = make_uint4(hw[4 * j], hw[4 * j + 1],
                                   hw[4 * j + 2], hw[4 * j + 3]);
        }

        // block max of ||f~||^2
        float n2 = 0.f;
#pragma unroll
        for (int o = 0; o < 8; o++) n2 += fa[o] * fa[o];
#pragma unroll
        for (int o = 16; o > 0; o >>= 1)
            n2 = fmaxf(n2, __shfl_xor_sync(0xffffffffu, n2, o));
        if ((t & 31) == 0) part[t >> 5] = n2;
        __syncthreads();
        if (t == 0) {
            float m = part[0];
#pragma unroll
            for (int i = 1; i < 8; i++) m = fmaxf(m, part[i]);
            d_fmax2[blockIdx.x - 3] = m;
        }
    }
}

// ===========================================================================
// K2: flash attention, tensor-core, KT=64, QT=128, SPLIT-K over 2 CTAs.
//   blockIdx.z = key half (tiles z*72 .. z*72+71). Writes partial (O~, l)
//   to global scratch; the softmax shift depends only on (q, Fmax) so the
//   two halves' partials are additive. 288 CTAs -> 2 CTAs/SM, 4 warps/SMSP.
// ===========================================================================
__global__ void __launch_bounds__(256, 2) attn_kernel(
        const float* __restrict__ bk,
        float* __restrict__ pO_out,
        float* __restrict__ pl_out) {
    __shared__ __align__(16) uint32_t hbuf[3][2048];   // 3 x 8KB fp16 H tiles
    __shared__ float g_sh[QT * 9];
    __shared__ float red8[8];

    int t    = threadIdx.x;
    int wid  = t >> 5;
    int lane = t & 31;
    int qt   = blockIdx.x;
    int b    = blockIdx.y;
    int z    = blockIdx.z;

    float iq = d_invsig[0], ik = d_invsig[1];

    // stage g tile (scaled + bias): 128 queries
    const float* gp = d_g + ((size_t)b * NN + (size_t)qt * QT) * 8;
    for (int i = t; i < QT * 8; i += 256)
        g_sh[(i >> 3) * 9 + (i & 7)] = ik * gp[i] + __ldg(bk + (i & 7));

    // Fmax^2 reduction (72 values)
    {
        float fm = (t < 72) ? d_fmax2[t] : 0.f;
#pragma unroll
        for (int o = 16; o > 0; o >>= 1)
            fm = fmaxf(fm, __shfl_xor_sync(0xffffffffu, fm, o));
        if (lane == 0) red8[wid] = fm;
    }

    // H staging role + prologue cp.async for this half's tiles 0,1
    int srow = t >> 3, sj = t & 7;
    const char* hsrc = (const char*)d_h16
                     + ((size_t)(b * NN + z * NTH * KT + srow)) * 128 + sj * 16;
    uint32_t hb0  = smem_u32(&hbuf[0][0]);
    uint32_t sdst = hb0 + srow * 128 + ((sj ^ (srow & 7)) << 4);
    cpasync16(sdst, hsrc);
    cpasync16(sdst + 4096, hsrc + 4096);
    CP_COMMIT();
    cpasync16(sdst + 8192, hsrc + 8192);
    cpasync16(sdst + 8192 + 4096, hsrc + 8192 + 4096);
    CP_COMMIT();

    __syncthreads();
    float Fmax;
    {
        float fm = red8[0];
#pragma unroll
        for (int i = 1; i < 8; i++) fm = fmaxf(fm, red8[i]);
        Fmax = sqrtf(fm);
    }

    // G B-fragments (fp16 hi/lo) for 2 query groups
    uint32_t bgh[2], bgl[2];
#pragma unroll
    for (int qg = 0; qg < 2; qg++) {
        int qn = 16 * wid + 8 * qg + (lane >> 2);
        int d0 = 2 * (lane & 3);
        float g0 = g_sh[qn * 9 + d0];
        float g1 = g_sh[qn * 9 + d0 + 1];
        __half h0 = __float2half_rn(g0);
        __half h1 = __float2half_rn(g1);
        bgh[qg] = ((uint32_t)__half_as_ushort(h1) << 16) | __half_as_ushort(h0);
        bgl[qg] = pack_f16(g1 - __half2float(h1), g0 - __half2float(h0));
    }

    // exp2 constants (identical for both key halves)
    float iq2 = iq * LOG2E;
    float cq2[2][2];
#pragma unroll
    for (int qg = 0; qg < 2; qg++) {
        int qa = 16 * wid + 8 * qg + 2 * (lane & 3);
#pragma unroll
        for (int u = 0; u < 2; u++) {
            float n2 = 0.f;
#pragma unroll
            for (int d = 0; d < 8; d++) {
                float v = g_sh[(qa + u) * 9 + d];
                n2 += v * v;
            }
            cq2[qg][u] = (SHIFT - iq * Fmax * sqrtf(n2)) * LOG2E;
        }
    }

    // ldsm.trans A-frag address pieces
    int lm = lane & 7, g1b = (lane >> 3) & 1, g2b = lane >> 4;
    uint32_t rowbase = hb0 + (g2b * 8 + lm) * 128;
    uint32_t colX[4];
#pragma unroll
    for (int ct = 0; ct < 4; ct++)
        colX[ct] = (uint32_t)(((2 * ct + g1b) ^ lm) << 4);

    float acc[4][2][4];
#pragma unroll
    for (int i = 0; i < 4; i++)
#pragma unroll
        for (int qg = 0; qg < 2; qg++)
#pragma unroll
            for (int j = 0; j < 4; j++) acc[i][qg][j] = 0.f;
    float ls[2][2] = {{0.f, 0.f}, {0.f, 0.f}};

    const uint4* fbase = (const uint4*)d_f16
                       + ((size_t)b * NTL + (size_t)z * NTH * 4) * 32 + lane;

    for (int kt = 0; kt < NTH; kt++) {
        int cur = kt % 3;

        if (kt < NTH - 1)
            asm volatile("cp.async.wait_group 1;" ::: "memory");
        else
            asm volatile("cp.async.wait_group 0;" ::: "memory");
        __syncthreads();

        if (kt + 2 < NTH) {
            uint32_t nb = ((kt + 2) % 3) * 8192;
            const char* hs = hsrc + (size_t)(kt + 2) * 8192;
            cpasync16(sdst + nb, hs);
            cpasync16(sdst + nb + 4096, hs + 4096);
            CP_COMMIT();
        }

        // f fragments for this tile (occupancy hides L2 latency)
        uint4 fA[4];
#pragma unroll
        for (int mt = 0; mt < 4; mt++)
            fA[mt] = __ldg(fbase + (size_t)(kt * 4 + mt) * 32);

        // ---- scores: fp16 mma, 2 q-groups ----
        uint32_t Bh[4][2][2];
#pragma unroll
        for (int mt = 0; mt < 4; mt++) {
#pragma unroll
            for (int qg = 0; qg < 2; qg++) {
                float D[4] = {0.f, 0.f, 0.f, 0.f};
                mma16h(D, fA[mt].x, fA[mt].y, fA[mt].z, fA[mt].w,
                       bgh[qg], bgh[qg]);
                mma16h(D, fA[mt].x, fA[mt].y, fA[mt].z, fA[mt].w,
                       bgl[qg], bgl[qg]);

                float p0 = ex2(fmaf(iq2, D[0], cq2[qg][0]));
                float p1 = ex2(fmaf(iq2, D[1], cq2[qg][1]));
                float p2 = ex2(fmaf(iq2, D[2], cq2[qg][0]));
                float p3 = ex2(fmaf(iq2, D[3], cq2[qg][1]));
                ls[qg][0] += p0 + p2;
                ls[qg][1] += p1 + p3;

                Bh[mt][qg][0] = movm(pack_f16(p1, p0));
                Bh[mt][qg][1] = movm(pack_f16(p3, p2));
            }
        }

        // ---- PV: O += H~ * P (each ldsm feeds 2 mma) ----
        uint32_t bufo = cur * 8192;
#pragma unroll
        for (int ct = 0; ct < 4; ct++) {
#pragma unroll
            for (int ks = 0; ks < 4; ks++) {
                uint32_t a0, a1, a2, a3;
                ldsm4t(a0, a1, a2, a3,
                       rowbase + bufo + ks * 2048 + colX[ct]);
                mma16h(acc[ct][0], a0, a1, a2, a3, Bh[ks][0][0], Bh[ks][0][1]);
                mma16h(acc[ct][1], a0, a1, a2, a3, Bh[ks][1][0], Bh[ks][1][1]);
            }
        }
    }

    // ---- partial denominators (sums, no reciprocal) ----
#pragma unroll
    for (int qg = 0; qg < 2; qg++) {
#pragma unroll
        for (int u = 0; u < 2; u++) {
            float v = ls[qg][u];
            v += __shfl_xor_sync(0xffffffffu, v, 4);
            v += __shfl_xor_sync(0xffffffffu, v, 8);
            v += __shfl_xor_sync(0xffffffffu, v, 16);
            ls[qg][u] = v;
        }
    }

    // ---- write partials ----
    size_t pb = (((size_t)b * NQT + qt) * 2 + z);
    float* pO = pO_out + pb * (CC * QT);
    if (lane < 4) {
#pragma unroll
        for (int qg = 0; qg < 2; qg++) {
            int q0 = 16 * wid + 8 * qg + 2 * lane;
            pl_out[pb * QT + q0]     = ls[qg][0];
            pl_out[pb * QT + q0 + 1] = ls[qg][1];
        }
    }
#pragma unroll
    for (int ct = 0; ct < 4; ct++) {
        int c0 = ct * 16 + (lane >> 2);
#pragma unroll
        for (int qg = 0; qg < 2; qg++) {
            int q0 = 16 * wid + 8 * qg + 2 * (lane & 3);
            float2 v0 = make_float2(acc[ct][qg][0], acc[ct][qg][1]);
            float2 v1 = make_float2(acc[ct][qg][2], acc[ct][qg][3]);
            *(float2*)(pO + c0 * QT + q0) = v0;
            *(float2*)(pO + (c0 + 8) * QT + q0) = v1;
        }
    }
}

// ===========================================================================
// K3: combine the 2 key-half partials + epilogue.
//   out = gam*iv*(O0+O1)/(l0+l1) + gam*bv + x
// Grid (72, BB), 256 threads; each thread: 1 channel x 32 queries (8 float4).
// ===========================================================================
__global__ void __launch_bounds__(256) combine_kernel(
        const float* __restrict__ x,
        const float* __restrict__ bv,
        const float* __restrict__ gamma,
        float* __restrict__ out) {
    __shared__ float linv[QT];
    int t  = threadIdx.x;
    int qt = blockIdx.x;
    int b  = blockIdx.y;

    size_t pb = ((size_t)b * NQT + qt) * 2;
    if (t < QT) {
        float l = d_pl[pb * QT + t] + d_pl[(pb + 1) * QT + t];
        linv[t] = 1.f / l;
    }
    __syncthreads();

    float gam = gamma[0];
    float giv = gam * d_invsig[2];
    const float* p0 = d_pO + pb * (CC * QT);
    const float* p1 = p0 + CC * QT;

    int c  = t >> 2;
    int qs = (t & 3) * 32;
    float gb = gam * __ldg(bv + c);
    size_t xb = ((size_t)b * CC + c) * NN + (size_t)qt * QT;

#pragma unroll
    for (int j = 0; j < 8; j++) {
        int q = qs + 4 * j;
        float4 a  = *(const float4*)(p0 + c * QT + q);
        float4 bb = *(const float4*)(p1 + c * QT + q);
        float4 xin = *(const float4*)(x + xb + q);
        float4 r;
        r.x = giv * (a.x + bb.x) * linv[q]     + gb + xin.x;
        r.y = giv * (a.y + bb.y) * linv[q + 1] + gb + xin.y;
        r.z = giv * (a.z + bb.z) * linv[q + 2] + gb + xin.z;
        r.w = giv * (a.w + bb.w) * linv[q + 3] + gb + xin.w;
        *(float4*)(out + xb + q) = r;
    }
}

// ===========================================================================
extern "C" void kernel_launch(void* const* d_in, const int* in_sizes, int n_in,
                              void* d_out, int out_size) {
    const float* x     = (const float*)d_in[0];
    const float* Wq    = (const float*)d_in[1];
    const float* bk    = (const float*)d_in[4];
    const float* Wk    = (const float*)d_in[3];
    const float* Wv    = (const float*)d_in[5];
    const float* bv    = (const float*)d_in[6];
    const float* gamma = (const float*)d_in[7];
    float* out = (float*)d_out;

    float* pO;
    float* pl;
    cudaGetSymbolAddress((void**)&pO, d_pO);
    cudaGetSymbolAddress((void**)&pl, d_pl);

    prep_kernel<<<3 + (BB * NN) / 256, 256>>>(x, Wq, Wk, Wv);
    attn_kernel<<<dim3(NQT, BB, 2), 256>>>(bk, pO, pl);
    combine_kernel<<<dim3(NQT, BB), 256>>>(x, bv, gamma, out);
}